// round 3
// baseline (speedup 1.0000x reference)
#include <cuda_runtime.h>

typedef unsigned long long ull;

// Problem constants
#define Bn   8
#define Sn   1024
#define Dn   512
#define Hn   8
#define DHn  64
#define BHn  (Bn * Hn)      // 64
#define Mn   (Bn * Sn)      // 8192
#define SCALE 0.044194173824159216f   // 1/sqrt(512)

// Scratch (device globals — no allocation allowed). 336 MB total.
static __device__ float g_q[Mn * Dn];
static __device__ float g_k[Mn * Dn];
static __device__ float g_v[Mn * Dn];
static __device__ float g_p[Mn * Dn];
static __device__ float g_ctx[Mn * Dn];
static __device__ float g_sc[(size_t)BHn * Sn * Sn];

// Packed dual-FMA (B300 FFMA2, only reachable via PTX)
#define FMA2(c, a, b) asm("fma.rn.f32x2 %0, %1, %2, %0;" : "+l"(c) : "l"(a), "l"(b))

// ---------------------------------------------------------------------------
// Shared 16-deep K microstep. Asd holds A DUPLICATED (Asd[k][2i]=Asd[k][2i+1]
// =A[i][k]) so both FFMA2 operands arrive packed from LDS.128.
// acc[8][4] ull = 8 rows x 8 cols (4 packed pairs).
// ---------------------------------------------------------------------------
__device__ __forceinline__ void mma16(const float* __restrict__ Asd,
                                      const float* __restrict__ Bs,
                                      int ASTR, int BSTR,
                                      int aoff /*=ty*16 floats*/,
                                      int boff /*=tx*8 floats*/,
                                      ull acc[8][4]) {
    #pragma unroll
    for (int k = 0; k < 16; k++) {
        const ulonglong2* ap = reinterpret_cast<const ulonglong2*>(Asd + k * ASTR + aoff);
        const ulonglong2* bp = reinterpret_cast<const ulonglong2*>(Bs + k * BSTR + boff);
        ulonglong2 a0 = ap[0], a1 = ap[1], a2 = ap[2], a3 = ap[3];
        ulonglong2 b0 = bp[0], b1 = bp[1];
        ull av[8] = {a0.x, a0.y, a1.x, a1.y, a2.x, a2.y, a3.x, a3.y};
        ull bv[4] = {b0.x, b0.y, b1.x, b1.y};
        #pragma unroll
        for (int i = 0; i < 8; i++)
            #pragma unroll
            for (int j = 0; j < 4; j++)
                FMA2(acc[i][j], av[i], bv[j]);
    }
}

// A loader, 256 threads, 128 rows x 16 k, k-contiguous source, dup-store.
__device__ __forceinline__ void load_a_dup256(float* Asd, int ASTR,
                                              const float* __restrict__ A, int lda,
                                              int k0, int tid) {
    const int row = tid >> 1;
    const int kh = (tid & 1) * 8;
    const float4* src = reinterpret_cast<const float4*>(A + (size_t)row * lda + k0 + kh);
    float4 v0 = src[0], v1 = src[1];
    float vals[8] = {v0.x, v0.y, v0.z, v0.w, v1.x, v1.y, v1.z, v1.w};
    #pragma unroll
    for (int q = 0; q < 8; q++) {
        float2 d; d.x = vals[q]; d.y = vals[q];
        *reinterpret_cast<float2*>(Asd + (kh + q) * ASTR + 2 * row) = d;
    }
}

// Same, with per-k bias added (score kernels: q + u/v bias).
__device__ __forceinline__ void load_a_dup256_bias(float* Asd, int ASTR,
                                                   const float* __restrict__ A, int lda,
                                                   const float* __restrict__ biask,
                                                   int k0, int tid) {
    const int row = tid >> 1;
    const int kh = (tid & 1) * 8;
    const float4* src = reinterpret_cast<const float4*>(A + (size_t)row * lda + k0 + kh);
    float4 v0 = src[0], v1 = src[1];
    float vals[8] = {v0.x, v0.y, v0.z, v0.w, v1.x, v1.y, v1.z, v1.w};
    #pragma unroll
    for (int q = 0; q < 8; q++) {
        float d0 = vals[q] + biask[k0 + kh + q];
        float2 d; d.x = d0; d.y = d0;
        *reinterpret_cast<float2*>(Asd + (kh + q) * ASTR + 2 * row) = d;
    }
}

// A loader, 128 threads, 128 rows x 16 k (AV kernel).
__device__ __forceinline__ void load_a_dup128(float* Asd, int ASTR,
                                              const float* __restrict__ A, int lda,
                                              int k0, int tid) {
    const int row = tid;
    const float4* src = reinterpret_cast<const float4*>(A + (size_t)row * lda + k0);
    float4 v0 = src[0], v1 = src[1], v2 = src[2], v3 = src[3];
    float vals[16] = {v0.x, v0.y, v0.z, v0.w, v1.x, v1.y, v1.z, v1.w,
                      v2.x, v2.y, v2.z, v2.w, v3.x, v3.y, v3.z, v3.w};
    #pragma unroll
    for (int q = 0; q < 16; q++) {
        float2 d; d.x = vals[q]; d.y = vals[q];
        *reinterpret_cast<float2*>(Asd + q * ASTR + 2 * row) = d;
    }
}

// B loader, natural [k][n] layout, 256 threads, 16 rows x 128 cols.
__device__ __forceinline__ void load_b_nat256(float* Bs, int BSTR,
                                              const float* __restrict__ B, int ldb,
                                              int k0, int tid) {
    const int row = tid >> 4;
    const int col = (tid & 15) * 8;
    const float4* src = reinterpret_cast<const float4*>(B + (size_t)(k0 + row) * ldb + col);
    float4 v0 = src[0], v1 = src[1];
    float4* dst = reinterpret_cast<float4*>(Bs + row * BSTR + col);
    dst[0] = v0; dst[1] = v1;
}

// B loader, natural [k][n], 128 threads, 16 rows x 64 cols (AV kernel).
__device__ __forceinline__ void load_b_nat128(float* Bs, int BSTR,
                                              const float* __restrict__ B, int ldb,
                                              int k0, int tid) {
    const int row = tid >> 3;
    const int col = (tid & 7) * 8;
    const float4* src = reinterpret_cast<const float4*>(B + (size_t)(k0 + row) * ldb + col);
    float4 v0 = src[0], v1 = src[1];
    float4* dst = reinterpret_cast<float4*>(Bs + row * BSTR + col);
    dst[0] = v0; dst[1] = v1;
}

// B loader, transposed source [j][k] -> Bs[k][j], 256 threads, 128 j x 16 k.
__device__ __forceinline__ void load_b_trans256(float* Bs, int BSTR,
                                                const float* __restrict__ B, int ldb,
                                                int k0, int tid) {
    const int j = tid >> 1;
    const int kh = (tid & 1) * 8;
    const float4* src = reinterpret_cast<const float4*>(B + (size_t)j * ldb + k0 + kh);
    float4 v0 = src[0], v1 = src[1];
    float vals[8] = {v0.x, v0.y, v0.z, v0.w, v1.x, v1.y, v1.z, v1.w};
    #pragma unroll
    for (int q = 0; q < 8; q++)
        Bs[(kh + q) * BSTR + j] = vals[q];
}

__device__ __forceinline__ float accf(const ull acc[8][4], int i, int j) {
    float2 f2 = *reinterpret_cast<const float2*>(&acc[i][j >> 1]);
    return (j & 1) ? f2.y : f2.x;
}

// ---------------------------------------------------------------------------
// Projection GEMM: C[8192,512] = X @ W (+bias). 128x128 tile, 8x8 micro.
// ---------------------------------------------------------------------------
__global__ __launch_bounds__(256) void proj_gemm(const float* __restrict__ X,
                                                 const float* __restrict__ W,
                                                 const float* __restrict__ bias,
                                                 int dst_sel) {
    float* C = (dst_sel == 0) ? g_q : (dst_sel == 1) ? g_k : (dst_sel == 2) ? g_v : g_p;
    __shared__ float Asd[16 * 256];
    __shared__ float Bs[16 * 128];
    const int tid = threadIdx.x;
    const int tx = tid & 15, ty = tid >> 4;
    const int mb = blockIdx.y * 128, nb = blockIdx.x * 128;
    const float* A = X + (size_t)mb * Dn;
    const float* Bb = W + nb;
    ull acc[8][4] = {};
    for (int k0 = 0; k0 < Dn; k0 += 16) {
        load_a_dup256(Asd, 256, A, Dn, k0, tid);
        load_b_nat256(Bs, 128, Bb, Dn, k0, tid);
        __syncthreads();
        mma16(Asd, Bs, 256, 128, ty * 16, tx * 8, acc);
        __syncthreads();
    }
    #pragma unroll
    for (int ii = 0; ii < 8; ii++) {
        const int m = mb + ty * 8 + ii;
        float* crow = C + (size_t)m * Dn + nb + tx * 8;
        #pragma unroll
        for (int half = 0; half < 2; half++) {
            float2 p0 = *reinterpret_cast<float2*>(&acc[ii][half * 2 + 0]);
            float2 p1 = *reinterpret_cast<float2*>(&acc[ii][half * 2 + 1]);
            float4 o;
            if (bias) {
                const float* bn = bias + nb + tx * 8 + half * 4;
                o.x = p0.x + bn[0]; o.y = p0.y + bn[1];
                o.z = p1.x + bn[2]; o.w = p1.y + bn[3];
            } else {
                o.x = p0.x; o.y = p0.y; o.z = p1.x; o.w = p1.y;
            }
            *reinterpret_cast<float4*>(crow + half * 4) = o;
        }
    }
}

// ---------------------------------------------------------------------------
// Output GEMM: out = g_ctx @ Wo + bo.
// ---------------------------------------------------------------------------
__global__ __launch_bounds__(256) void out_gemm(const float* __restrict__ W,
                                                const float* __restrict__ bias,
                                                float* __restrict__ C) {
    __shared__ float Asd[16 * 256];
    __shared__ float Bs[16 * 128];
    const int tid = threadIdx.x;
    const int tx = tid & 15, ty = tid >> 4;
    const int mb = blockIdx.y * 128, nb = blockIdx.x * 128;
    const float* A = g_ctx + (size_t)mb * Dn;
    const float* Bb = W + nb;
    ull acc[8][4] = {};
    for (int k0 = 0; k0 < Dn; k0 += 16) {
        load_a_dup256(Asd, 256, A, Dn, k0, tid);
        load_b_nat256(Bs, 128, Bb, Dn, k0, tid);
        __syncthreads();
        mma16(Asd, Bs, 256, 128, ty * 16, tx * 8, acc);
        __syncthreads();
    }
    #pragma unroll
    for (int ii = 0; ii < 8; ii++) {
        const int m = mb + ty * 8 + ii;
        float* crow = C + (size_t)m * Dn + nb + tx * 8;
        const float* bn = bias + nb + tx * 8;
        #pragma unroll
        for (int half = 0; half < 2; half++) {
            float2 p0 = *reinterpret_cast<float2*>(&acc[ii][half * 2 + 0]);
            float2 p1 = *reinterpret_cast<float2*>(&acc[ii][half * 2 + 1]);
            float4 o;
            o.x = p0.x + bn[half * 4 + 0]; o.y = p0.y + bn[half * 4 + 1];
            o.z = p1.x + bn[half * 4 + 2]; o.w = p1.y + bn[half * 4 + 3];
            *reinterpret_cast<float4*>(crow + half * 4) = o;
        }
    }
}

// ---------------------------------------------------------------------------
// Score GEMMs, per (b,h). 128x128 tile over K=64.
// Pass 0 (SHIFT=0, hb=v_bias): P[i,c]=(q_i+vb).p_c scattered shifted into g_sc:
//   c >= S-1-i -> R[i, c-S+1+i];  c < S-1-i -> R[i-1, c+i+1] (dropped at i==0)
// Pass 1 (SHIFT=1, hb=u_bias): g_sc[i,j] = (content + (j==i+1?0:g_sc[i,j]))*SCALE
// ---------------------------------------------------------------------------
template <int SHIFT>
__global__ __launch_bounds__(256) void score_gemm(const float* __restrict__ hb) {
    const int bh = blockIdx.z;
    const int b = bh >> 3, h = bh & 7;
    const int ib = blockIdx.y * 128, jb = blockIdx.x * 128;
    const float* A = g_q + (size_t)b * Sn * Dn + h * DHn + (size_t)ib * Dn;
    const float* Bsrc = ((SHIFT ? g_k : g_p) + (size_t)b * Sn * Dn + h * DHn) + (size_t)jb * Dn;
    const float* biask = hb + h * DHn;
    __shared__ float Asd[16 * 256];
    __shared__ float Bs[16 * 132];
    const int tid = threadIdx.x;
    const int tx = tid & 15, ty = tid >> 4;
    ull acc[8][4] = {};
    for (int k0 = 0; k0 < DHn; k0 += 16) {
        load_a_dup256_bias(Asd, 256, A, Dn, biask, k0, tid);
        load_b_trans256(Bs, 132, Bsrc, Dn, k0, tid);
        __syncthreads();
        mma16(Asd, Bs, 256, 132, ty * 16, tx * 8, acc);
        __syncthreads();
    }
    const size_t base = (size_t)bh * Sn * Sn;
    if (SHIFT) {
        #pragma unroll
        for (int ii = 0; ii < 8; ii++) {
            const int i = ib + ty * 8 + ii;
            float* row = g_sc + base + (size_t)i * Sn;
            #pragma unroll
            for (int half = 0; half < 2; half++) {
                const int j0 = jb + tx * 8 + half * 4;
                float4 ps = *reinterpret_cast<float4*>(row + j0);
                float pv[4] = {ps.x, ps.y, ps.z, ps.w};
                float4 o;
                float* ov = reinterpret_cast<float*>(&o);
                #pragma unroll
                for (int q = 0; q < 4; q++) {
                    const int j = j0 + q;
                    float p = (j == i + 1) ? 0.0f : pv[q];
                    ov[q] = (accf(acc, ii, half * 4 + q) + p) * SCALE;
                }
                *reinterpret_cast<float4*>(row + j0) = o;
            }
        }
    } else {
        #pragma unroll
        for (int ii = 0; ii < 8; ii++) {
            const int i = ib + ty * 8 + ii;
            #pragma unroll
            for (int jj = 0; jj < 8; jj++) {
                const int j = jb + tx * 8 + jj;
                const float val = accf(acc, ii, jj);
                if (j >= Sn - 1 - i)
                    g_sc[base + (size_t)i * Sn + (j - Sn + 1 + i)] = val;
                else if (i > 0)
                    g_sc[base + (size_t)(i - 1) * Sn + (j + i + 1)] = val;
            }
        }
    }
}

// ---------------------------------------------------------------------------
// Row softmax over g_sc, in-place.
// ---------------------------------------------------------------------------
__global__ void softmax_rows() {
    float* r = g_sc + (size_t)blockIdx.x * Sn;
    const int t = threadIdx.x;
    float4 v = reinterpret_cast<float4*>(r)[t];
    float m = fmaxf(fmaxf(v.x, v.y), fmaxf(v.z, v.w));
    #pragma unroll
    for (int o = 16; o; o >>= 1) m = fmaxf(m, __shfl_xor_sync(0xffffffffu, m, o));
    __shared__ float red[8];
    if ((t & 31) == 0) red[t >> 5] = m;
    __syncthreads();
    float bmax = red[0];
    #pragma unroll
    for (int i = 1; i < 8; i++) bmax = fmaxf(bmax, red[i]);
    __syncthreads();
    v.x = __expf(v.x - bmax); v.y = __expf(v.y - bmax);
    v.z = __expf(v.z - bmax); v.w = __expf(v.w - bmax);
    float s = v.x + v.y + v.z + v.w;
    #pragma unroll
    for (int o = 16; o; o >>= 1) s += __shfl_xor_sync(0xffffffffu, s, o);
    if ((t & 31) == 0) red[t >> 5] = s;
    __syncthreads();
    float tot = 0.0f;
    #pragma unroll
    for (int i = 0; i < 8; i++) tot += red[i];
    const float inv = 1.0f / tot;
    v.x *= inv; v.y *= inv; v.z *= inv; v.w *= inv;
    reinterpret_cast<float4*>(r)[t] = v;
}

// ---------------------------------------------------------------------------
// Context GEMM, per (b,h): ctx = atten @ v. 128x64 tile, 128 threads, 8x8.
// ---------------------------------------------------------------------------
__global__ __launch_bounds__(128) void av_gemm() {
    const int bh = blockIdx.y;
    const int b = bh >> 3, h = bh & 7;
    const int ib = blockIdx.x * 128;
    const float* A = g_sc + (size_t)bh * Sn * Sn + (size_t)ib * Sn;
    const float* Bsrc = g_v + (size_t)b * Sn * Dn + h * DHn;
    __shared__ float Asd[16 * 256];
    __shared__ float Bs[16 * 64];
    const int tid = threadIdx.x;
    const int tx = tid & 7, ty = tid >> 3;
    ull acc[8][4] = {};
    for (int k0 = 0; k0 < Sn; k0 += 16) {
        load_a_dup128(Asd, 256, A, Sn, k0, tid);
        load_b_nat128(Bs, 64, Bsrc, Dn, k0, tid);
        __syncthreads();
        mma16(Asd, Bs, 256, 64, ty * 16, tx * 8, acc);
        __syncthreads();
    }
    #pragma unroll
    for (int ii = 0; ii < 8; ii++) {
        const int i = ib + ty * 8 + ii;
        float* crow = g_ctx + (size_t)(b * Sn + i) * Dn + h * DHn + tx * 8;
        #pragma unroll
        for (int half = 0; half < 2; half++) {
            float2 p0 = *reinterpret_cast<float2*>(&acc[ii][half * 2 + 0]);
            float2 p1 = *reinterpret_cast<float2*>(&acc[ii][half * 2 + 1]);
            float4 o; o.x = p0.x; o.y = p0.y; o.z = p1.x; o.w = p1.y;
            *reinterpret_cast<float4*>(crow + half * 4) = o;
        }
    }
}

// ---------------------------------------------------------------------------
extern "C" void kernel_launch(void* const* d_in, const int* in_sizes, int n_in,
                              void* d_out, int out_size) {
    (void)in_sizes; (void)n_in; (void)out_size;
    const float* query = (const float*)d_in[0];
    const float* key   = (const float*)d_in[1];
    const float* value = (const float*)d_in[2];
    const float* pemb  = (const float*)d_in[3];
    const float* Wq    = (const float*)d_in[4];
    const float* bq    = (const float*)d_in[5];
    const float* Wk    = (const float*)d_in[6];
    const float* bk    = (const float*)d_in[7];
    const float* Wv    = (const float*)d_in[8];
    const float* bv    = (const float*)d_in[9];
    const float* Wp    = (const float*)d_in[10];
    const float* u_bias = (const float*)d_in[11];
    const float* v_bias = (const float*)d_in[12];
    const float* Wo    = (const float*)d_in[13];
    const float* bo    = (const float*)d_in[14];
    float* out = (float*)d_out;

    dim3 gproj(Dn / 128, Mn / 128);       // (4, 64)
    proj_gemm<<<gproj, 256>>>(query, Wq, bq, 0);
    proj_gemm<<<gproj, 256>>>(key,   Wk, bk, 1);
    proj_gemm<<<gproj, 256>>>(value, Wv, bv, 2);
    proj_gemm<<<gproj, 256>>>(pemb,  Wp, nullptr, 3);

    dim3 gsc(Sn / 128, Sn / 128, BHn);    // (8, 8, 64)
    score_gemm<0><<<gsc, 256>>>(v_bias);  // pos scores scattered (shifted) -> g_sc
    score_gemm<1><<<gsc, 256>>>(u_bias);  // content + pos, scaled -> g_sc

    softmax_rows<<<BHn * Sn, 256>>>();

    dim3 gav(Sn / 128, BHn);              // (8, 64)
    av_gemm<<<gav, 128>>>();

    out_gemm<<<gproj, 256>>>(Wo, bo, out);
}

// round 4
// speedup vs baseline: 1.2643x; 1.2643x over previous
#include <cuda_runtime.h>

// Problem constants
#define Bn   8
#define Sn   1024
#define Dn   512
#define Hn   8
#define DHn  64
#define BHn  (Bn * Hn)      // 64
#define Mn   (Bn * Sn)      // 8192
#define SCALE 0.044194173824159216f   // 1/sqrt(512)

#define ASTR 132   // padded smem stride for transposed A (and transposed B)

// Scratch (device globals — no allocation allowed). 336 MB total.
static __device__ float g_q[Mn * Dn];
static __device__ float g_k[Mn * Dn];
static __device__ float g_v[Mn * Dn];
static __device__ float g_p[Mn * Dn];
static __device__ float g_ctx[Mn * Dn];
static __device__ float g_sc[(size_t)BHn * Sn * Sn];

// ---------------------------------------------------------------------------
// 8-deep K microstep: classic sgemm inner loop.
// As: [8][ASTR] transposed A (As[k][m]); Bs: [8][BSTR] natural (Bs[k][n]).
// ---------------------------------------------------------------------------
template <int BSTR>
__device__ __forceinline__ void mma8(const float* __restrict__ As,
                                     const float* __restrict__ Bs,
                                     int aoff, int boff, float acc[8][8]) {
    #pragma unroll
    for (int k = 0; k < 8; k++) {
        float4 a0 = *reinterpret_cast<const float4*>(As + k * ASTR + aoff);
        float4 a1 = *reinterpret_cast<const float4*>(As + k * ASTR + aoff + 4);
        float4 b0 = *reinterpret_cast<const float4*>(Bs + k * BSTR + boff);
        float4 b1 = *reinterpret_cast<const float4*>(Bs + k * BSTR + boff + 4);
        float a[8] = {a0.x, a0.y, a0.z, a0.w, a1.x, a1.y, a1.z, a1.w};
        float b[8] = {b0.x, b0.y, b0.z, b0.w, b1.x, b1.y, b1.z, b1.w};
        #pragma unroll
        for (int i = 0; i < 8; i++)
            #pragma unroll
            for (int j = 0; j < 8; j++)
                acc[i][j] = fmaf(a[i], b[j], acc[i][j]);
    }
}

// A loader (256 thr): 128 rows x 8 k from row-major [*, lda], store transposed.
__device__ __forceinline__ void load_a_t256(float* As, const float* __restrict__ A,
                                            int lda, int k0, int tid) {
    const int row = tid >> 1;
    const int kc = (tid & 1) * 4;
    float4 v = *reinterpret_cast<const float4*>(A + (size_t)row * lda + k0 + kc);
    As[(kc + 0) * ASTR + row] = v.x;
    As[(kc + 1) * ASTR + row] = v.y;
    As[(kc + 2) * ASTR + row] = v.z;
    As[(kc + 3) * ASTR + row] = v.w;
}

// Same with per-k bias (score kernels).
__device__ __forceinline__ void load_a_t256_bias(float* As, const float* __restrict__ A,
                                                 int lda, const float* __restrict__ biask,
                                                 int k0, int tid) {
    const int row = tid >> 1;
    const int kc = (tid & 1) * 4;
    float4 v = *reinterpret_cast<const float4*>(A + (size_t)row * lda + k0 + kc);
    As[(kc + 0) * ASTR + row] = v.x + biask[k0 + kc + 0];
    As[(kc + 1) * ASTR + row] = v.y + biask[k0 + kc + 1];
    As[(kc + 2) * ASTR + row] = v.z + biask[k0 + kc + 2];
    As[(kc + 3) * ASTR + row] = v.w + biask[k0 + kc + 3];
}

// B loader (256 thr): natural [k][n], 8 rows x 128 cols.
__device__ __forceinline__ void load_b_n256(float* Bs, const float* __restrict__ B,
                                            int ldb, int k0, int tid) {
    const int row = tid >> 5;
    const int col = (tid & 31) * 4;
    *reinterpret_cast<float4*>(Bs + row * 128 + col) =
        *reinterpret_cast<const float4*>(B + (size_t)(k0 + row) * ldb + col);
}

// B loader (256 thr): transposed source [j][k] -> Bs[k][j], 128 j x 8 k.
__device__ __forceinline__ void load_b_t256(float* Bs, const float* __restrict__ B,
                                            int ldb, int k0, int tid) {
    const int j = tid >> 1;
    const int kc = (tid & 1) * 4;
    float4 v = *reinterpret_cast<const float4*>(B + (size_t)j * ldb + k0 + kc);
    Bs[(kc + 0) * ASTR + j] = v.x;
    Bs[(kc + 1) * ASTR + j] = v.y;
    Bs[(kc + 2) * ASTR + j] = v.z;
    Bs[(kc + 3) * ASTR + j] = v.w;
}

// ---------------------------------------------------------------------------
// Projection GEMM: C[8192,512] = X @ W (+bias). 128x128 tile, 8x8 micro.
// ---------------------------------------------------------------------------
__global__ __launch_bounds__(256, 2) void proj_gemm(const float* __restrict__ X,
                                                    const float* __restrict__ W,
                                                    const float* __restrict__ bias,
                                                    int dst_sel) {
    float* C = (dst_sel == 0) ? g_q : (dst_sel == 1) ? g_k : (dst_sel == 2) ? g_v : g_p;
    __shared__ float As[8 * ASTR];
    __shared__ float Bs[8 * 128];
    const int tid = threadIdx.x;
    const int tx = tid & 15, ty = tid >> 4;
    const int mb = blockIdx.y * 128, nb = blockIdx.x * 128;
    const float* A = X + (size_t)mb * Dn;
    const float* Bb = W + nb;
    float acc[8][8] = {};
    for (int k0 = 0; k0 < Dn; k0 += 8) {
        load_a_t256(As, A, Dn, k0, tid);
        load_b_n256(Bs, Bb, Dn, k0, tid);
        __syncthreads();
        mma8<128>(As, Bs, ty * 8, tx * 8, acc);
        __syncthreads();
    }
    #pragma unroll
    for (int ii = 0; ii < 8; ii++) {
        float* crow = C + (size_t)(mb + ty * 8 + ii) * Dn + nb + tx * 8;
        if (bias) {
            const float* bn = bias + nb + tx * 8;
            #pragma unroll
            for (int jj = 0; jj < 8; jj++) acc[ii][jj] += bn[jj];
        }
        *reinterpret_cast<float4*>(crow + 0) = *reinterpret_cast<float4*>(&acc[ii][0]);
        *reinterpret_cast<float4*>(crow + 4) = *reinterpret_cast<float4*>(&acc[ii][4]);
    }
}

// ---------------------------------------------------------------------------
// Output GEMM: out = g_ctx @ Wo + bo.
// ---------------------------------------------------------------------------
__global__ __launch_bounds__(256, 2) void out_gemm(const float* __restrict__ W,
                                                   const float* __restrict__ bias,
                                                   float* __restrict__ C) {
    __shared__ float As[8 * ASTR];
    __shared__ float Bs[8 * 128];
    const int tid = threadIdx.x;
    const int tx = tid & 15, ty = tid >> 4;
    const int mb = blockIdx.y * 128, nb = blockIdx.x * 128;
    const float* A = g_ctx + (size_t)mb * Dn;
    const float* Bb = W + nb;
    float acc[8][8] = {};
    for (int k0 = 0; k0 < Dn; k0 += 8) {
        load_a_t256(As, A, Dn, k0, tid);
        load_b_n256(Bs, Bb, Dn, k0, tid);
        __syncthreads();
        mma8<128>(As, Bs, ty * 8, tx * 8, acc);
        __syncthreads();
    }
    #pragma unroll
    for (int ii = 0; ii < 8; ii++) {
        float* crow = C + (size_t)(mb + ty * 8 + ii) * Dn + nb + tx * 8;
        const float* bn = bias + nb + tx * 8;
        #pragma unroll
        for (int jj = 0; jj < 8; jj++) acc[ii][jj] += bn[jj];
        *reinterpret_cast<float4*>(crow + 0) = *reinterpret_cast<float4*>(&acc[ii][0]);
        *reinterpret_cast<float4*>(crow + 4) = *reinterpret_cast<float4*>(&acc[ii][4]);
    }
}

// ---------------------------------------------------------------------------
// Score GEMMs, per (b,h). 128x128 tile over K=64.
// Pass 0 (SHIFT=0, hb=v_bias): P[i,c]=(q_i+vb).p_c scattered shifted into g_sc:
//   c >= S-1-i -> R[i, c-S+1+i];  c < S-1-i -> R[i-1, c+i+1] (dropped at i==0)
// Pass 1 (SHIFT=1, hb=u_bias): g_sc[i,j] = (content + (j==i+1?0:g_sc[i,j]))*SCALE
// ---------------------------------------------------------------------------
template <int SHIFT>
__global__ __launch_bounds__(256, 2) void score_gemm(const float* __restrict__ hb) {
    const int bh = blockIdx.z;
    const int b = bh >> 3, h = bh & 7;
    const int ib = blockIdx.y * 128, jb = blockIdx.x * 128;
    const float* A = g_q + (size_t)b * Sn * Dn + h * DHn + (size_t)ib * Dn;
    const float* Bsrc = ((SHIFT ? g_k : g_p) + (size_t)b * Sn * Dn + h * DHn) + (size_t)jb * Dn;
    const float* biask = hb + h * DHn;
    __shared__ float As[8 * ASTR];
    __shared__ float Bs[8 * ASTR];
    const int tid = threadIdx.x;
    const int tx = tid & 15, ty = tid >> 4;
    float acc[8][8] = {};
    for (int k0 = 0; k0 < DHn; k0 += 8) {
        load_a_t256_bias(As, A, Dn, biask, k0, tid);
        load_b_t256(Bs, Bsrc, Dn, k0, tid);
        __syncthreads();
        mma8<ASTR>(As, Bs, ty * 8, tx * 8, acc);
        __syncthreads();
    }
    const size_t base = (size_t)bh * Sn * Sn;
    if (SHIFT) {
        #pragma unroll
        for (int ii = 0; ii < 8; ii++) {
            const int i = ib + ty * 8 + ii;
            float* row = g_sc + base + (size_t)i * Sn;
            #pragma unroll
            for (int half = 0; half < 2; half++) {
                const int j0 = jb + tx * 8 + half * 4;
                float4 ps = *reinterpret_cast<float4*>(row + j0);
                float pv[4] = {ps.x, ps.y, ps.z, ps.w};
                float4 o;
                float* ov = reinterpret_cast<float*>(&o);
                #pragma unroll
                for (int q = 0; q < 4; q++) {
                    const int j = j0 + q;
                    float p = (j == i + 1) ? 0.0f : pv[q];
                    ov[q] = (acc[ii][half * 4 + q] + p) * SCALE;
                }
                *reinterpret_cast<float4*>(row + j0) = o;
            }
        }
    } else {
        #pragma unroll
        for (int ii = 0; ii < 8; ii++) {
            const int i = ib + ty * 8 + ii;
            #pragma unroll
            for (int jj = 0; jj < 8; jj++) {
                const int j = jb + tx * 8 + jj;
                const float val = acc[ii][jj];
                if (j >= Sn - 1 - i)
                    g_sc[base + (size_t)i * Sn + (j - Sn + 1 + i)] = val;
                else if (i > 0)
                    g_sc[base + (size_t)(i - 1) * Sn + (j + i + 1)] = val;
            }
        }
    }
}

// ---------------------------------------------------------------------------
// Row softmax over g_sc, in-place. One block per row.
// ---------------------------------------------------------------------------
__global__ void softmax_rows() {
    float* r = g_sc + (size_t)blockIdx.x * Sn;
    const int t = threadIdx.x;
    float4 v = reinterpret_cast<float4*>(r)[t];
    float m = fmaxf(fmaxf(v.x, v.y), fmaxf(v.z, v.w));
    #pragma unroll
    for (int o = 16; o; o >>= 1) m = fmaxf(m, __shfl_xor_sync(0xffffffffu, m, o));
    __shared__ float red[8];
    if ((t & 31) == 0) red[t >> 5] = m;
    __syncthreads();
    float bmax = red[0];
    #pragma unroll
    for (int i = 1; i < 8; i++) bmax = fmaxf(bmax, red[i]);
    __syncthreads();
    v.x = __expf(v.x - bmax); v.y = __expf(v.y - bmax);
    v.z = __expf(v.z - bmax); v.w = __expf(v.w - bmax);
    float s = v.x + v.y + v.z + v.w;
    #pragma unroll
    for (int o = 16; o; o >>= 1) s += __shfl_xor_sync(0xffffffffu, s, o);
    if ((t & 31) == 0) red[t >> 5] = s;
    __syncthreads();
    float tot = 0.0f;
    #pragma unroll
    for (int i = 0; i < 8; i++) tot += red[i];
    const float inv = 1.0f / tot;
    v.x *= inv; v.y *= inv; v.z *= inv; v.w *= inv;
    reinterpret_cast<float4*>(r)[t] = v;
}

// ---------------------------------------------------------------------------
// Context GEMM, per (b,h): ctx = atten @ v. 128x64 tile, 128 threads, 8x8.
// ---------------------------------------------------------------------------
__global__ __launch_bounds__(128, 4) void av_gemm() {
    const int bh = blockIdx.y;
    const int b = bh >> 3, h = bh & 7;
    const int ib = blockIdx.x * 128;
    const float* A = g_sc + (size_t)bh * Sn * Sn + (size_t)ib * Sn;
    const float* Bsrc = g_v + (size_t)b * Sn * Dn + h * DHn;
    __shared__ float As[8 * ASTR];
    __shared__ float Bs[8 * 64];
    const int tid = threadIdx.x;
    const int tx = tid & 7, ty = tid >> 3;   // 8 x 16 thread grid
    float acc[8][8] = {};
    for (int k0 = 0; k0 < Sn; k0 += 8) {
        // A: 128 rows x 8 k, 128 threads -> 8 floats each (two float4)
        {
            const int row = tid;
            float4 v0 = *reinterpret_cast<const float4*>(A + (size_t)row * Sn + k0);
            float4 v1 = *reinterpret_cast<const float4*>(A + (size_t)row * Sn + k0 + 4);
            As[0 * ASTR + row] = v0.x; As[1 * ASTR + row] = v0.y;
            As[2 * ASTR + row] = v0.z; As[3 * ASTR + row] = v0.w;
            As[4 * ASTR + row] = v1.x; As[5 * ASTR + row] = v1.y;
            As[6 * ASTR + row] = v1.z; As[7 * ASTR + row] = v1.w;
        }
        // B: 8 rows x 64 cols, 128 threads -> float4 each
        {
            const int row = tid >> 4;
            const int col = (tid & 15) * 4;
            *reinterpret_cast<float4*>(Bs + row * 64 + col) =
                *reinterpret_cast<const float4*>(Bsrc + (size_t)(k0 + row) * Dn + col);
        }
        __syncthreads();
        mma8<64>(As, Bs, ty * 8, tx * 8, acc);
        __syncthreads();
    }
    #pragma unroll
    for (int ii = 0; ii < 8; ii++) {
        const int i = ib + ty * 8 + ii;
        float* crow = g_ctx + (size_t)(b * Sn + i) * Dn + h * DHn + tx * 8;
        *reinterpret_cast<float4*>(crow + 0) = *reinterpret_cast<float4*>(&acc[ii][0]);
        *reinterpret_cast<float4*>(crow + 4) = *reinterpret_cast<float4*>(&acc[ii][4]);
    }
}

// ---------------------------------------------------------------------------
extern "C" void kernel_launch(void* const* d_in, const int* in_sizes, int n_in,
                              void* d_out, int out_size) {
    (void)in_sizes; (void)n_in; (void)out_size;
    const float* query = (const float*)d_in[0];
    const float* key   = (const float*)d_in[1];
    const float* value = (const float*)d_in[2];
    const float* pemb  = (const float*)d_in[3];
    const float* Wq    = (const float*)d_in[4];
    const float* bq    = (const float*)d_in[5];
    const float* Wk    = (const float*)d_in[6];
    const float* bk    = (const float*)d_in[7];
    const float* Wv    = (const float*)d_in[8];
    const float* bv    = (const float*)d_in[9];
    const float* Wp    = (const float*)d_in[10];
    const float* u_bias = (const float*)d_in[11];
    const float* v_bias = (const float*)d_in[12];
    const float* Wo    = (const float*)d_in[13];
    const float* bo    = (const float*)d_in[14];
    float* out = (float*)d_out;

    dim3 gproj(Dn / 128, Mn / 128);       // (4, 64)
    proj_gemm<<<gproj, 256>>>(query, Wq, bq, 0);
    proj_gemm<<<gproj, 256>>>(key,   Wk, bk, 1);
    proj_gemm<<<gproj, 256>>>(value, Wv, bv, 2);
    proj_gemm<<<gproj, 256>>>(pemb,  Wp, nullptr, 3);

    dim3 gsc(Sn / 128, Sn / 128, BHn);    // (8, 8, 64)
    score_gemm<0><<<gsc, 256>>>(v_bias);  // pos scores scattered (shifted) -> g_sc
    score_gemm<1><<<gsc, 256>>>(u_bias);  // content + pos, scaled -> g_sc

    softmax_rows<<<BHn * Sn, 256>>>();

    dim3 gav(Sn / 128, BHn);              // (8, 64)
    av_gemm<<<gav, 128>>>();

    out_gemm<<<gproj, 256>>>(Wo, bo, out);
}

// round 6
// speedup vs baseline: 1.3008x; 1.0289x over previous
#include <cuda_runtime.h>

// Problem constants
#define Bn   8
#define Sn   1024
#define Dn   512
#define Hn   8
#define DHn  64
#define BHn  (Bn * Hn)      // 64
#define Mn   (Bn * Sn)      // 8192
#define SCALE 0.044194173824159216f   // 1/sqrt(512)

#define KC    16     // K chunk per smem stage
#define AS    20     // A smem stride (floats): (20*g+kq)%32 distinct -> conflict-free frags
#define NS128 136    // B smem stride for BN=128: 136%32==8 -> (8*kq+g)%32 distinct
#define NS64  72     // B smem stride for BN=64:   72%32==8

// Scratch (device globals — no allocation allowed). 336 MB total.
static __device__ float g_q[Mn * Dn];
static __device__ float g_k[Mn * Dn];
static __device__ float g_v[Mn * Dn];
static __device__ float g_p[Mn * Dn];
static __device__ float g_ctx[Mn * Dn];
static __device__ float g_sc[(size_t)BHn * Sn * Sn];

// ---------------------------------------------------------------------------
// Tensor-core primitives
// ---------------------------------------------------------------------------
__device__ __forceinline__ void mma_tf32(float c[4], const unsigned a[4],
                                         unsigned b0, unsigned b1) {
    asm volatile(
        "mma.sync.aligned.m16n8k8.row.col.f32.tf32.tf32.f32 "
        "{%0,%1,%2,%3},{%4,%5,%6,%7},{%8,%9},{%0,%1,%2,%3};"
        : "+f"(c[0]), "+f"(c[1]), "+f"(c[2]), "+f"(c[3])
        : "r"(a[0]), "r"(a[1]), "r"(a[2]), "r"(a[3]), "r"(b0), "r"(b1));
}

// fp32 -> (tf32 hi, tf32 lo) split for 3xTF32 emulation (~2^-21 rel error)
__device__ __forceinline__ void split2(float x, float& hi, float& lo) {
    unsigned h; asm("cvt.rna.tf32.f32 %0, %1;" : "=r"(h) : "f"(x));
    float hf = __uint_as_float(h);
    float lf = x - hf;
    unsigned l; asm("cvt.rna.tf32.f32 %0, %1;" : "=r"(l) : "f"(lf));
    hi = hf; lo = __uint_as_float(l);
}

// ---------------------------------------------------------------------------
// Warp compute: one KC=16 chunk. Warp tile = 64 x (NT*8).
// As: [128][AS] row-major (m,k). Bs: [KC][NS] (k,n).
// acc[mtile=4][NT][4] per m16n8k8 accumulator mapping.
// ---------------------------------------------------------------------------
template <int NT, int NS>
__device__ __forceinline__ void warp_mma16(const float* __restrict__ Ah,
                                           const float* __restrict__ Al,
                                           const float* __restrict__ Bh,
                                           const float* __restrict__ Bl,
                                           int wm, int wn, int lane,
                                           float acc[4][NT][4]) {
    const int g = lane >> 2, kq = lane & 3;
    #pragma unroll
    for (int kk = 0; kk < KC; kk += 8) {
        unsigned ah[4][4], al[4][4];
        #pragma unroll
        for (int t = 0; t < 4; t++) {
            const int m0 = (wm + t * 16 + g) * AS + kk + kq;
            ah[t][0] = __float_as_uint(Ah[m0]);
            ah[t][1] = __float_as_uint(Ah[m0 + 8 * AS]);
            ah[t][2] = __float_as_uint(Ah[m0 + 4]);
            ah[t][3] = __float_as_uint(Ah[m0 + 8 * AS + 4]);
            al[t][0] = __float_as_uint(Al[m0]);
            al[t][1] = __float_as_uint(Al[m0 + 8 * AS]);
            al[t][2] = __float_as_uint(Al[m0 + 4]);
            al[t][3] = __float_as_uint(Al[m0 + 8 * AS + 4]);
        }
        #pragma unroll
        for (int u = 0; u < NT; u++) {
            const int nbi = (kk + kq) * NS + wn + u * 8 + g;
            unsigned bh0 = __float_as_uint(Bh[nbi]);
            unsigned bh1 = __float_as_uint(Bh[nbi + 4 * NS]);
            unsigned bl0 = __float_as_uint(Bl[nbi]);
            unsigned bl1 = __float_as_uint(Bl[nbi + 4 * NS]);
            #pragma unroll
            for (int t = 0; t < 4; t++) {
                mma_tf32(acc[t][u], ah[t], bl0, bl1);
                mma_tf32(acc[t][u], al[t], bh0, bh1);
                mma_tf32(acc[t][u], ah[t], bh0, bh1);
            }
        }
    }
}

// ---------------------------------------------------------------------------
// Stage loaders (256 threads unless noted)
// ---------------------------------------------------------------------------
// A: 128 rows x KC k from row-major [*, lda] (+ optional bias over k)
template <bool HASB>
__device__ __forceinline__ void load_a16(float* Ah, float* Al,
                                         const float* __restrict__ A, int lda,
                                         const float* __restrict__ biask,
                                         int k0, int tid) {
    const int row = tid >> 1;
    const int kc = (tid & 1) * 8;
    const float4* src = reinterpret_cast<const float4*>(A + (size_t)row * lda + k0 + kc);
    float4 v0 = src[0], v1 = src[1];
    float vals[8] = {v0.x, v0.y, v0.z, v0.w, v1.x, v1.y, v1.z, v1.w};
    #pragma unroll
    for (int q = 0; q < 8; q++) {
        float x = vals[q];
        if (HASB) x += biask[k0 + kc + q];
        split2(x, Ah[row * AS + kc + q], Al[row * AS + kc + q]);
    }
}

// B natural [k][n], BN=128
__device__ __forceinline__ void load_b16_n128(float* Bh, float* Bl,
                                              const float* __restrict__ B, int ldb,
                                              int k0, int tid) {
    const int row = tid >> 4;
    const int col = (tid & 15) * 8;
    const float4* src = reinterpret_cast<const float4*>(B + (size_t)(k0 + row) * ldb + col);
    float4 v0 = src[0], v1 = src[1];
    float vals[8] = {v0.x, v0.y, v0.z, v0.w, v1.x, v1.y, v1.z, v1.w};
    #pragma unroll
    for (int q = 0; q < 8; q++)
        split2(vals[q], Bh[row * NS128 + col + q], Bl[row * NS128 + col + q]);
}

// B natural [k][n], BN=64
__device__ __forceinline__ void load_b16_n64(float* Bh, float* Bl,
                                             const float* __restrict__ B, int ldb,
                                             int k0, int tid) {
    const int row = tid >> 4;
    const int col = (tid & 15) * 4;
    float4 v = *reinterpret_cast<const float4*>(B + (size_t)(k0 + row) * ldb + col);
    float vals[4] = {v.x, v.y, v.z, v.w};
    #pragma unroll
    for (int q = 0; q < 4; q++)
        split2(vals[q], Bh[row * NS64 + col + q], Bl[row * NS64 + col + q]);
}

// B transposed source [j][k] -> Bs[k][j], 128 j x KC k (score kernels)
__device__ __forceinline__ void load_b16_t128(float* Bh, float* Bl,
                                              const float* __restrict__ B, int ldb,
                                              int k0, int tid) {
    const int j = tid >> 1;
    const int kc = (tid & 1) * 8;
    const float4* src = reinterpret_cast<const float4*>(B + (size_t)j * ldb + k0 + kc);
    float4 v0 = src[0], v1 = src[1];
    float vals[8] = {v0.x, v0.y, v0.z, v0.w, v1.x, v1.y, v1.z, v1.w};
    #pragma unroll
    for (int q = 0; q < 8; q++)
        split2(vals[q], Bh[(kc + q) * NS128 + j], Bl[(kc + q) * NS128 + j]);
}

// ---------------------------------------------------------------------------
// Projection GEMM: C[8192,512] = X @ W (+bias). 128x128 tile, tensor cores.
// ---------------------------------------------------------------------------
__global__ __launch_bounds__(256, 2) void proj_gemm(const float* __restrict__ X,
                                                    const float* __restrict__ W,
                                                    const float* __restrict__ bias,
                                                    int dst_sel) {
    float* C = (dst_sel == 0) ? g_q : (dst_sel == 1) ? g_k : (dst_sel == 2) ? g_v : g_p;
    __shared__ float Ah[128 * AS], Al[128 * AS];
    __shared__ float Bh[KC * NS128], Bl[KC * NS128];
    const int tid = threadIdx.x, lane = tid & 31, w = tid >> 5;
    const int wm = (w >> 2) * 64, wn = (w & 3) * 32;
    const int mb = blockIdx.y * 128, nb = blockIdx.x * 128;
    float acc[4][4][4] = {};
    for (int k0 = 0; k0 < Dn; k0 += KC) {
        load_a16<false>(Ah, Al, X + (size_t)mb * Dn, Dn, nullptr, k0, tid);
        load_b16_n128(Bh, Bl, W + nb, Dn, k0, tid);
        __syncthreads();
        warp_mma16<4, NS128>(Ah, Al, Bh, Bl, wm, wn, lane, acc);
        __syncthreads();
    }
    const int g = lane >> 2, kq = lane & 3;
    #pragma unroll
    for (int t = 0; t < 4; t++) {
        #pragma unroll
        for (int u = 0; u < 4; u++) {
            const int row = mb + wm + t * 16 + g;
            const int col = nb + wn + u * 8 + 2 * kq;
            float b0 = 0.f, b1 = 0.f;
            if (bias) { b0 = bias[col]; b1 = bias[col + 1]; }
            float2 lo; lo.x = acc[t][u][0] + b0; lo.y = acc[t][u][1] + b1;
            float2 hi; hi.x = acc[t][u][2] + b0; hi.y = acc[t][u][3] + b1;
            *reinterpret_cast<float2*>(C + (size_t)row * Dn + col) = lo;
            *reinterpret_cast<float2*>(C + (size_t)(row + 8) * Dn + col) = hi;
        }
    }
}

// ---------------------------------------------------------------------------
// Output GEMM: out = g_ctx @ Wo + bo.
// ---------------------------------------------------------------------------
__global__ __launch_bounds__(256, 2) void out_gemm(const float* __restrict__ W,
                                                   const float* __restrict__ bias,
                                                   float* __restrict__ C) {
    __shared__ float Ah[128 * AS], Al[128 * AS];
    __shared__ float Bh[KC * NS128], Bl[KC * NS128];
    const int tid = threadIdx.x, lane = tid & 31, w = tid >> 5;
    const int wm = (w >> 2) * 64, wn = (w & 3) * 32;
    const int mb = blockIdx.y * 128, nb = blockIdx.x * 128;
    float acc[4][4][4] = {};
    for (int k0 = 0; k0 < Dn; k0 += KC) {
        load_a16<false>(Ah, Al, g_ctx + (size_t)mb * Dn, Dn, nullptr, k0, tid);
        load_b16_n128(Bh, Bl, W + nb, Dn, k0, tid);
        __syncthreads();
        warp_mma16<4, NS128>(Ah, Al, Bh, Bl, wm, wn, lane, acc);
        __syncthreads();
    }
    const int g = lane >> 2, kq = lane & 3;
    #pragma unroll
    for (int t = 0; t < 4; t++) {
        #pragma unroll
        for (int u = 0; u < 4; u++) {
            const int row = mb + wm + t * 16 + g;
            const int col = nb + wn + u * 8 + 2 * kq;
            const float b0 = bias[col], b1 = bias[col + 1];
            float2 lo; lo.x = acc[t][u][0] + b0; lo.y = acc[t][u][1] + b1;
            float2 hi; hi.x = acc[t][u][2] + b0; hi.y = acc[t][u][3] + b1;
            *reinterpret_cast<float2*>(C + (size_t)row * Dn + col) = lo;
            *reinterpret_cast<float2*>(C + (size_t)(row + 8) * Dn + col) = hi;
        }
    }
}

// ---------------------------------------------------------------------------
// Score GEMMs, per (b,h). 128x128 tile over K=64, tensor cores.
// Pass 0 (SHIFT=0, hb=v_bias): P[i,c]=(q_i+vb).p_c scattered shifted into g_sc:
//   c >= S-1-i -> R[i, c-S+1+i];  c < S-1-i -> R[i-1, c+i+1] (dropped at i==0)
// Pass 1 (SHIFT=1, hb=u_bias): g_sc[i,j] = (content + (j==i+1?0:g_sc[i,j]))*SCALE
// ---------------------------------------------------------------------------
template <int SHIFT>
__global__ __launch_bounds__(256, 2) void score_gemm(const float* __restrict__ hb) {
    const int bh = blockIdx.z;
    const int b = bh >> 3, h = bh & 7;
    const int ib = blockIdx.y * 128, jb = blockIdx.x * 128;
    const float* A = g_q + (size_t)b * Sn * Dn + h * DHn + (size_t)ib * Dn;
    const float* Bsrc = ((SHIFT ? g_k : g_p) + (size_t)b * Sn * Dn + h * DHn) + (size_t)jb * Dn;
    const float* biask = hb + h * DHn;
    __shared__ float Ah[128 * AS], Al[128 * AS];
    __shared__ float Bh[KC * NS128], Bl[KC * NS128];
    const int tid = threadIdx.x, lane = tid & 31, w = tid >> 5;
    const int wm = (w >> 2) * 64, wn = (w & 3) * 32;
    float acc[4][4][4] = {};
    #pragma unroll
    for (int k0 = 0; k0 < DHn; k0 += KC) {
        load_a16<true>(Ah, Al, A, Dn, biask, k0, tid);
        load_b16_t128(Bh, Bl, Bsrc, Dn, k0, tid);
        __syncthreads();
        warp_mma16<4, NS128>(Ah, Al, Bh, Bl, wm, wn, lane, acc);
        __syncthreads();
    }
    const size_t base = (size_t)bh * Sn * Sn;
    const int g = lane >> 2, kq = lane & 3;
    #pragma unroll
    for (int t = 0; t < 4; t++) {
        #pragma unroll
        for (int u = 0; u < 4; u++) {
            #pragma unroll
            for (int e = 0; e < 4; e++) {
                const int i = ib + wm + t * 16 + g + (e >= 2 ? 8 : 0);
                const int j = jb + wn + u * 8 + 2 * kq + (e & 1);
                const float val = acc[t][u][e];
                if (SHIFT) {
                    float p = (j == i + 1) ? 0.0f : g_sc[base + (size_t)i * Sn + j];
                    g_sc[base + (size_t)i * Sn + j] = (val + p) * SCALE;
                } else {
                    if (j >= Sn - 1 - i)
                        g_sc[base + (size_t)i * Sn + (j - Sn + 1 + i)] = val;
                    else if (i > 0)
                        g_sc[base + (size_t)(i - 1) * Sn + (j + i + 1)] = val;
                }
            }
        }
    }
}

// ---------------------------------------------------------------------------
// Row softmax over g_sc, in-place.
// ---------------------------------------------------------------------------
__global__ void softmax_rows() {
    float* r = g_sc + (size_t)blockIdx.x * Sn;
    const int t = threadIdx.x;
    float4 v = reinterpret_cast<float4*>(r)[t];
    float m = fmaxf(fmaxf(v.x, v.y), fmaxf(v.z, v.w));
    #pragma unroll
    for (int o = 16; o; o >>= 1) m = fmaxf(m, __shfl_xor_sync(0xffffffffu, m, o));
    __shared__ float red[8];
    if ((t & 31) == 0) red[t >> 5] = m;
    __syncthreads();
    float bmax = red[0];
    #pragma unroll
    for (int i = 1; i < 8; i++) bmax = fmaxf(bmax, red[i]);
    __syncthreads();
    v.x = __expf(v.x - bmax); v.y = __expf(v.y - bmax);
    v.z = __expf(v.z - bmax); v.w = __expf(v.w - bmax);
    float s = v.x + v.y + v.z + v.w;
    #pragma unroll
    for (int o = 16; o; o >>= 1) s += __shfl_xor_sync(0xffffffffu, s, o);
    if ((t & 31) == 0) red[t >> 5] = s;
    __syncthreads();
    float tot = 0.0f;
    #pragma unroll
    for (int i = 0; i < 8; i++) tot += red[i];
    const float inv = 1.0f / tot;
    v.x *= inv; v.y *= inv; v.z *= inv; v.w *= inv;
    reinterpret_cast<float4*>(r)[t] = v;
}

// ---------------------------------------------------------------------------
// Context GEMM, per (b,h): ctx = atten @ v. 128m x 64n tile, K=1024.
// 8 warps of 64x16 (NT=2).
// ---------------------------------------------------------------------------
__global__ __launch_bounds__(256, 2) void av_gemm() {
    const int bh = blockIdx.y;
    const int b = bh >> 3, h = bh & 7;
    const int ib = blockIdx.x * 128;
    const float* A = g_sc + (size_t)bh * Sn * Sn + (size_t)ib * Sn;
    const float* Bsrc = g_v + (size_t)b * Sn * Dn + h * DHn;
    __shared__ float Ah[128 * AS], Al[128 * AS];
    __shared__ float Bh[KC * NS64], Bl[KC * NS64];
    const int tid = threadIdx.x, lane = tid & 31, w = tid >> 5;
    const int wm = (w >> 2) * 64, wn = (w & 3) * 16;
    float acc[4][2][4] = {};
    for (int k0 = 0; k0 < Sn; k0 += KC) {
        load_a16<false>(Ah, Al, A, Sn, nullptr, k0, tid);
        load_b16_n64(Bh, Bl, Bsrc, Dn, k0, tid);
        __syncthreads();
        warp_mma16<2, NS64>(Ah, Al, Bh, Bl, wm, wn, lane, acc);
        __syncthreads();
    }
    const int g = lane >> 2, kq = lane & 3;
    #pragma unroll
    for (int t = 0; t < 4; t++) {
        #pragma unroll
        for (int u = 0; u < 2; u++) {
            const int i = ib + wm + t * 16 + g;
            const int col = h * DHn + wn + u * 8 + 2 * kq;
            float2 lo; lo.x = acc[t][u][0]; lo.y = acc[t][u][1];
            float2 hi; hi.x = acc[t][u][2]; hi.y = acc[t][u][3];
            *reinterpret_cast<float2*>(g_ctx + (size_t)(b * Sn + i) * Dn + col) = lo;
            *reinterpret_cast<float2*>(g_ctx + (size_t)(b * Sn + i + 8) * Dn + col) = hi;
        }
    }
}

// ---------------------------------------------------------------------------
extern "C" void kernel_launch(void* const* d_in, const int* in_sizes, int n_in,
                              void* d_out, int out_size) {
    (void)in_sizes; (void)n_in; (void)out_size;
    const float* query = (const float*)d_in[0];
    const float* key   = (const float*)d_in[1];
    const float* value = (const float*)d_in[2];
    const float* pemb  = (const float*)d_in[3];
    const float* Wq    = (const float*)d_in[4];
    const float* bq    = (const float*)d_in[5];
    const float* Wk    = (const float*)d_in[6];
    const float* bk    = (const float*)d_in[7];
    const float* Wv    = (const float*)d_in[8];
    const float* bv    = (const float*)d_in[9];
    const float* Wp    = (const float*)d_in[10];
    const float* u_bias = (const float*)d_in[11];
    const float* v_bias = (const float*)d_in[12];
    const float* Wo    = (const float*)d_in[13];
    const float* bo    = (const float*)d_in[14];
    float* out = (float*)d_out;

    dim3 gproj(Dn / 128, Mn / 128);       // (4, 64)
    proj_gemm<<<gproj, 256>>>(query, Wq, bq, 0);
    proj_gemm<<<gproj, 256>>>(key,   Wk, bk, 1);
    proj_gemm<<<gproj, 256>>>(value, Wv, bv, 2);
    proj_gemm<<<gproj, 256>>>(pemb,  Wp, nullptr, 3);

    dim3 gsc(Sn / 128, Sn / 128, BHn);    // (8, 8, 64)
    score_gemm<0><<<gsc, 256>>>(v_bias);  // pos scores scattered (shifted) -> g_sc
    score_gemm<1><<<gsc, 256>>>(u_bias);  // content + pos, scaled -> g_sc

    softmax_rows<<<BHn * Sn, 256>>>();

    dim3 gav(Sn / 128, BHn);              // (8, 64)
    av_gemm<<<gav, 256>>>();

    out_gemm<<<gproj, 256>>>(Wo, bo, out);
}

// round 7
// speedup vs baseline: 1.9048x; 1.4644x over previous
#include <cuda_runtime.h>
#include <cuda_bf16.h>

// Problem constants
#define Bn   8
#define Sn   1024
#define Dn   512
#define Hn   8
#define DHn  64
#define BHn  (Bn * Hn)      // 64
#define Mn   (Bn * Sn)      // 8192
#define SCALE 0.044194173824159216f   // 1/sqrt(512)

#define KC    16     // real-k per smem stage
#define AS    20     // A smem stride (u32): (20*g+kq)%32 distinct -> conflict-free
#define NS128 136    // B smem stride, BN=128: mod 32 == 8 -> conflict-free frags
#define NS64  72     // B smem stride, BN=64:  mod 32 == 8

// Scratch (device globals — no allocation allowed). 336 MB total.
static __device__ float g_q[Mn * Dn];
static __device__ float g_k[Mn * Dn];
static __device__ float g_v[Mn * Dn];
static __device__ float g_p[Mn * Dn];
static __device__ float g_ctx[Mn * Dn];
static __device__ float g_sc[(size_t)BHn * Sn * Sn];

// ---------------------------------------------------------------------------
// fp32 -> packed (bf16 hi | bf16 lo<<16). hi+lo == x to ~2^-18 rel.
// ---------------------------------------------------------------------------
__device__ __forceinline__ unsigned pack_split(float x) {
    __nv_bfloat16 h = __float2bfloat16(x);
    float hf = __bfloat162float(h);
    __nv_bfloat16 l = __float2bfloat16(x - hf);
    return (unsigned)__bfloat16_as_ushort(h) |
           ((unsigned)__bfloat16_as_ushort(l) << 16);
}

__device__ __forceinline__ unsigned swap16(unsigned u) { return (u >> 16) | (u << 16); }

__device__ __forceinline__ void mma_bf16(float c[4], const unsigned a[4],
                                         unsigned b0, unsigned b1) {
    asm volatile(
        "mma.sync.aligned.m16n8k16.row.col.f32.bf16.bf16.f32 "
        "{%0,%1,%2,%3},{%4,%5,%6,%7},{%8,%9},{%0,%1,%2,%3};"
        : "+f"(c[0]), "+f"(c[1]), "+f"(c[2]), "+f"(c[3])
        : "r"(a[0]), "r"(a[1]), "r"(a[2]), "r"(a[3]), "r"(b0), "r"(b1));
}

__device__ __forceinline__ void load8(float v[8], const float* __restrict__ p) {
    float4 a = *reinterpret_cast<const float4*>(p);
    float4 b = *reinterpret_cast<const float4*>(p + 4);
    v[0] = a.x; v[1] = a.y; v[2] = a.z; v[3] = a.w;
    v[4] = b.x; v[5] = b.y; v[6] = b.z; v[7] = b.w;
}

// ---------------------------------------------------------------------------
// Warp compute on one KC=16 stage. Warp tile 64 x (NT*8).
// A: [128][AS] packed (m, real-k). B: [KC][NS] packed (real-k, n).
// Exact fp32 product via dual-mma (normal + half-swapped B).
// ---------------------------------------------------------------------------
template <int NT, int NS>
__device__ __forceinline__ void warp_mma_stage(const unsigned* __restrict__ A,
                                               const unsigned* __restrict__ B,
                                               int wm, int wn, int lane,
                                               float acc[4][NT][4]) {
    const int g = lane >> 2, kq = lane & 3;
    #pragma unroll
    for (int h = 0; h < 2; h++) {          // two m16n8k16 steps = 16 real k
        unsigned af[4][4];
        #pragma unroll
        for (int t = 0; t < 4; t++) {
            const unsigned* p = A + (wm + t * 16 + g) * AS + h * 8 + kq;
            af[t][0] = p[0]; af[t][1] = p[8 * AS];
            af[t][2] = p[4]; af[t][3] = p[8 * AS + 4];
        }
        #pragma unroll
        for (int u = 0; u < NT; u++) {
            const unsigned* q = B + (h * 8 + kq) * NS + wn + u * 8 + g;
            unsigned b0 = q[0], b1 = q[4 * NS];
            unsigned s0 = swap16(b0), s1 = swap16(b1);
            #pragma unroll
            for (int t = 0; t < 4; t++) {
                mma_bf16(acc[t][u], af[t], b0, b1);   // hi*hi + lo*lo
                mma_bf16(acc[t][u], af[t], s0, s1);   // hi*lo + lo*hi
            }
        }
    }
}

// ---------------------------------------------------------------------------
// Projection GEMM: C[8192,512] = X @ W (+bias). 128x128 tile, double-buffered.
// ---------------------------------------------------------------------------
__global__ __launch_bounds__(256, 2) void proj_gemm(const float* __restrict__ X,
                                                    const float* __restrict__ W,
                                                    const float* __restrict__ bias,
                                                    int dst_sel) {
    float* C = (dst_sel == 0) ? g_q : (dst_sel == 1) ? g_k : (dst_sel == 2) ? g_v : g_p;
    __shared__ unsigned Asm[2][128 * AS];
    __shared__ unsigned Bsm[2][KC * NS128];
    const int tid = threadIdx.x, lane = tid & 31, w = tid >> 5;
    const int wm = (w >> 2) * 64, wn = (w & 3) * 32;
    const int mb = blockIdx.y * 128, nb = blockIdx.x * 128;
    const int ar = tid >> 1, akc = (tid & 1) * 8;
    const int br = tid >> 4, bc = (tid & 15) * 8;
    const float* Ag = X + (size_t)(mb + ar) * Dn + akc;
    const float* Bg = W + (size_t)br * Dn + nb + bc;
    float av[8], bv[8];
    load8(av, Ag); load8(bv, Bg);
    float acc[4][4][4] = {};
    int buf = 0;
    for (int k0 = 0; k0 < Dn; k0 += KC) {
        #pragma unroll
        for (int q = 0; q < 8; q++) {
            Asm[buf][ar * AS + akc + q] = pack_split(av[q]);
            Bsm[buf][br * NS128 + bc + q] = pack_split(bv[q]);
        }
        __syncthreads();
        if (k0 + KC < Dn) {
            load8(av, Ag + k0 + KC);
            load8(bv, Bg + (size_t)(k0 + KC) * Dn);
        }
        warp_mma_stage<4, NS128>(Asm[buf], Bsm[buf], wm, wn, lane, acc);
        buf ^= 1;
    }
    const int g = lane >> 2, kq = lane & 3;
    #pragma unroll
    for (int t = 0; t < 4; t++) {
        #pragma unroll
        for (int u = 0; u < 4; u++) {
            const int row = mb + wm + t * 16 + g;
            const int col = nb + wn + u * 8 + 2 * kq;
            float b0 = 0.f, b1 = 0.f;
            if (bias) { b0 = bias[col]; b1 = bias[col + 1]; }
            float2 lo; lo.x = acc[t][u][0] + b0; lo.y = acc[t][u][1] + b1;
            float2 hi; hi.x = acc[t][u][2] + b0; hi.y = acc[t][u][3] + b1;
            *reinterpret_cast<float2*>(C + (size_t)row * Dn + col) = lo;
            *reinterpret_cast<float2*>(C + (size_t)(row + 8) * Dn + col) = hi;
        }
    }
}

// ---------------------------------------------------------------------------
// Output GEMM: out = g_ctx @ Wo + bo.
// ---------------------------------------------------------------------------
__global__ __launch_bounds__(256, 2) void out_gemm(const float* __restrict__ W,
                                                   const float* __restrict__ bias,
                                                   float* __restrict__ C) {
    __shared__ unsigned Asm[2][128 * AS];
    __shared__ unsigned Bsm[2][KC * NS128];
    const int tid = threadIdx.x, lane = tid & 31, w = tid >> 5;
    const int wm = (w >> 2) * 64, wn = (w & 3) * 32;
    const int mb = blockIdx.y * 128, nb = blockIdx.x * 128;
    const int ar = tid >> 1, akc = (tid & 1) * 8;
    const int br = tid >> 4, bc = (tid & 15) * 8;
    const float* Ag = g_ctx + (size_t)(mb + ar) * Dn + akc;
    const float* Bg = W + (size_t)br * Dn + nb + bc;
    float av[8], bv[8];
    load8(av, Ag); load8(bv, Bg);
    float acc[4][4][4] = {};
    int buf = 0;
    for (int k0 = 0; k0 < Dn; k0 += KC) {
        #pragma unroll
        for (int q = 0; q < 8; q++) {
            Asm[buf][ar * AS + akc + q] = pack_split(av[q]);
            Bsm[buf][br * NS128 + bc + q] = pack_split(bv[q]);
        }
        __syncthreads();
        if (k0 + KC < Dn) {
            load8(av, Ag + k0 + KC);
            load8(bv, Bg + (size_t)(k0 + KC) * Dn);
        }
        warp_mma_stage<4, NS128>(Asm[buf], Bsm[buf], wm, wn, lane, acc);
        buf ^= 1;
    }
    const int g = lane >> 2, kq = lane & 3;
    #pragma unroll
    for (int t = 0; t < 4; t++) {
        #pragma unroll
        for (int u = 0; u < 4; u++) {
            const int row = mb + wm + t * 16 + g;
            const int col = nb + wn + u * 8 + 2 * kq;
            const float b0 = bias[col], b1 = bias[col + 1];
            float2 lo; lo.x = acc[t][u][0] + b0; lo.y = acc[t][u][1] + b1;
            float2 hi; hi.x = acc[t][u][2] + b0; hi.y = acc[t][u][3] + b1;
            *reinterpret_cast<float2*>(C + (size_t)row * Dn + col) = lo;
            *reinterpret_cast<float2*>(C + (size_t)(row + 8) * Dn + col) = hi;
        }
    }
}

// ---------------------------------------------------------------------------
// Score GEMMs, per (b,h). 128x128 tile over K=64, tensor cores.
// Pass 0 (SHIFT=0, hb=v_bias): P[i,c]=(q_i+vb).p_c scattered shifted into g_sc:
//   c >= S-1-i -> R[i, c-S+1+i];  c < S-1-i -> R[i-1, c+i+1] (dropped at i==0)
// Pass 1 (SHIFT=1, hb=u_bias): g_sc[i,j] = (content + (j==i+1?0:g_sc[i,j]))*SCALE
// ---------------------------------------------------------------------------
template <int SHIFT>
__global__ __launch_bounds__(256, 2) void score_gemm(const float* __restrict__ hb) {
    const int bh = blockIdx.z;
    const int b = bh >> 3, h = bh & 7;
    const int ib = blockIdx.y * 128, jb = blockIdx.x * 128;
    const float* Abase = g_q + (size_t)b * Sn * Dn + h * DHn + (size_t)ib * Dn;
    const float* Bbase = ((SHIFT ? g_k : g_p) + (size_t)b * Sn * Dn + h * DHn) + (size_t)jb * Dn;
    const float* biask = hb + h * DHn;
    __shared__ unsigned Asm[2][128 * AS];
    __shared__ unsigned Bsm[2][KC * NS128];
    const int tid = threadIdx.x, lane = tid & 31, w = tid >> 5;
    const int wm = (w >> 2) * 64, wn = (w & 3) * 32;
    const int ar = tid >> 1, akc = (tid & 1) * 8;
    const float* Ag = Abase + (size_t)ar * Dn + akc;
    const float* Bg = Bbase + (size_t)ar * Dn + akc;   // transposed source, same tiling
    float av[8], bv[8], bk[8];
    load8(av, Ag); load8(bv, Bg); load8(bk, biask + akc);
    float acc[4][4][4] = {};
    int buf = 0;
    #pragma unroll
    for (int k0 = 0; k0 < DHn; k0 += KC) {
        #pragma unroll
        for (int q = 0; q < 8; q++) {
            Asm[buf][ar * AS + akc + q] = pack_split(av[q] + bk[q]);
            Bsm[buf][(akc + q) * NS128 + ar] = pack_split(bv[q]);
        }
        __syncthreads();
        if (k0 + KC < DHn) {
            load8(av, Ag + k0 + KC);
            load8(bv, Bg + k0 + KC);
            load8(bk, biask + k0 + KC + akc);
        }
        warp_mma_stage<4, NS128>(Asm[buf], Bsm[buf], wm, wn, lane, acc);
        buf ^= 1;
    }
    const size_t base = (size_t)bh * Sn * Sn;
    const int g = lane >> 2, kq = lane & 3;
    #pragma unroll
    for (int t = 0; t < 4; t++) {
        #pragma unroll
        for (int u = 0; u < 4; u++) {
            #pragma unroll
            for (int e = 0; e < 4; e++) {
                const int i = ib + wm + t * 16 + g + (e >= 2 ? 8 : 0);
                const int j = jb + wn + u * 8 + 2 * kq + (e & 1);
                const float val = acc[t][u][e];
                if (SHIFT) {
                    float p = (j == i + 1) ? 0.0f : g_sc[base + (size_t)i * Sn + j];
                    g_sc[base + (size_t)i * Sn + j] = (val + p) * SCALE;
                } else {
                    if (j >= Sn - 1 - i)
                        g_sc[base + (size_t)i * Sn + (j - Sn + 1 + i)] = val;
                    else if (i > 0)
                        g_sc[base + (size_t)(i - 1) * Sn + (j + i + 1)] = val;
                }
            }
        }
    }
}

// ---------------------------------------------------------------------------
// Row softmax over g_sc, in-place.
// ---------------------------------------------------------------------------
__global__ void softmax_rows() {
    float* r = g_sc + (size_t)blockIdx.x * Sn;
    const int t = threadIdx.x;
    float4 v = reinterpret_cast<float4*>(r)[t];
    float m = fmaxf(fmaxf(v.x, v.y), fmaxf(v.z, v.w));
    #pragma unroll
    for (int o = 16; o; o >>= 1) m = fmaxf(m, __shfl_xor_sync(0xffffffffu, m, o));
    __shared__ float red[8];
    if ((t & 31) == 0) red[t >> 5] = m;
    __syncthreads();
    float bmax = red[0];
    #pragma unroll
    for (int i = 1; i < 8; i++) bmax = fmaxf(bmax, red[i]);
    __syncthreads();
    v.x = __expf(v.x - bmax); v.y = __expf(v.y - bmax);
    v.z = __expf(v.z - bmax); v.w = __expf(v.w - bmax);
    float s = v.x + v.y + v.z + v.w;
    #pragma unroll
    for (int o = 16; o; o >>= 1) s += __shfl_xor_sync(0xffffffffu, s, o);
    if ((t & 31) == 0) red[t >> 5] = s;
    __syncthreads();
    float tot = 0.0f;
    #pragma unroll
    for (int i = 0; i < 8; i++) tot += red[i];
    const float inv = 1.0f / tot;
    v.x *= inv; v.y *= inv; v.z *= inv; v.w *= inv;
    reinterpret_cast<float4*>(r)[t] = v;
}

// ---------------------------------------------------------------------------
// Context GEMM, per (b,h): ctx = atten @ v. 128m x 64n, K=1024.
// 8 warps of 64x16 (NT=2), double-buffered.
// ---------------------------------------------------------------------------
__global__ __launch_bounds__(256, 2) void av_gemm() {
    const int bh = blockIdx.y;
    const int b = bh >> 3, h = bh & 7;
    const int ib = blockIdx.x * 128;
    const float* Abase = g_sc + (size_t)bh * Sn * Sn + (size_t)ib * Sn;
    const float* Bbase = g_v + (size_t)b * Sn * Dn + h * DHn;
    __shared__ unsigned Asm[2][128 * AS];
    __shared__ unsigned Bsm[2][KC * NS64];
    const int tid = threadIdx.x, lane = tid & 31, w = tid >> 5;
    const int wm = (w >> 2) * 64, wn = (w & 3) * 16;
    const int ar = tid >> 1, akc = (tid & 1) * 8;
    const int br = tid >> 4, bc = (tid & 15) * 4;
    const float* Ag = Abase + (size_t)ar * Sn + akc;
    const float* Bg = Bbase + (size_t)br * Dn + bc;
    float av[8];
    float4 bq;
    load8(av, Ag);
    bq = *reinterpret_cast<const float4*>(Bg);
    float acc[4][2][4] = {};
    int buf = 0;
    for (int k0 = 0; k0 < Sn; k0 += KC) {
        #pragma unroll
        for (int q = 0; q < 8; q++)
            Asm[buf][ar * AS + akc + q] = pack_split(av[q]);
        {
            float bvals[4] = {bq.x, bq.y, bq.z, bq.w};
            #pragma unroll
            for (int q = 0; q < 4; q++)
                Bsm[buf][br * NS64 + bc + q] = pack_split(bvals[q]);
        }
        __syncthreads();
        if (k0 + KC < Sn) {
            load8(av, Ag + k0 + KC);
            bq = *reinterpret_cast<const float4*>(Bg + (size_t)(k0 + KC) * Dn);
        }
        warp_mma_stage<2, NS64>(Asm[buf], Bsm[buf], wm, wn, lane, acc);
        buf ^= 1;
    }
    const int g = lane >> 2, kq = lane & 3;
    #pragma unroll
    for (int t = 0; t < 4; t++) {
        #pragma unroll
        for (int u = 0; u < 2; u++) {
            const int i = ib + wm + t * 16 + g;
            const int col = h * DHn + wn + u * 8 + 2 * kq;
            float2 lo; lo.x = acc[t][u][0]; lo.y = acc[t][u][1];
            float2 hi; hi.x = acc[t][u][2]; hi.y = acc[t][u][3];
            *reinterpret_cast<float2*>(g_ctx + (size_t)(b * Sn + i) * Dn + col) = lo;
            *reinterpret_cast<float2*>(g_ctx + (size_t)(b * Sn + i + 8) * Dn + col) = hi;
        }
    }
}

// ---------------------------------------------------------------------------
extern "C" void kernel_launch(void* const* d_in, const int* in_sizes, int n_in,
                              void* d_out, int out_size) {
    (void)in_sizes; (void)n_in; (void)out_size;
    const float* query = (const float*)d_in[0];
    const float* key   = (const float*)d_in[1];
    const float* value = (const float*)d_in[2];
    const float* pemb  = (const float*)d_in[3];
    const float* Wq    = (const float*)d_in[4];
    const float* bq    = (const float*)d_in[5];
    const float* Wk    = (const float*)d_in[6];
    const float* bk    = (const float*)d_in[7];
    const float* Wv    = (const float*)d_in[8];
    const float* bv    = (const float*)d_in[9];
    const float* Wp    = (const float*)d_in[10];
    const float* u_bias = (const float*)d_in[11];
    const float* v_bias = (const float*)d_in[12];
    const float* Wo    = (const float*)d_in[13];
    const float* bo    = (const float*)d_in[14];
    float* out = (float*)d_out;

    dim3 gproj(Dn / 128, Mn / 128);       // (4, 64)
    proj_gemm<<<gproj, 256>>>(query, Wq, bq, 0);
    proj_gemm<<<gproj, 256>>>(key,   Wk, bk, 1);
    proj_gemm<<<gproj, 256>>>(value, Wv, bv, 2);
    proj_gemm<<<gproj, 256>>>(pemb,  Wp, nullptr, 3);

    dim3 gsc(Sn / 128, Sn / 128, BHn);    // (8, 8, 64)
    score_gemm<0><<<gsc, 256>>>(v_bias);  // pos scores scattered (shifted) -> g_sc
    score_gemm<1><<<gsc, 256>>>(u_bias);  // content + pos, scaled -> g_sc

    softmax_rows<<<BHn * Sn, 256>>>();

    dim3 gav(Sn / 128, BHn);              // (8, 64)
    av_gemm<<<gav, 256>>>();

    out_gemm<<<gproj, 256>>>(Wo, bo, out);
}

// round 8
// speedup vs baseline: 2.1224x; 1.1142x over previous
#include <cuda_runtime.h>
#include <cuda_bf16.h>

// Problem constants
#define Bn   8
#define Sn   1024
#define Dn   512
#define Hn   8
#define DHn  64
#define BHn  (Bn * Hn)      // 64
#define Mn   (Bn * Sn)      // 8192
#define SCALE 0.044194173824159216f   // 1/sqrt(512)

#define KC    16     // real-k per smem stage (GEMM kernels)
#define AS    20     // A smem stride (u32): (20*g+kq)%32 distinct -> conflict-free
#define NS128 136    // B smem stride, BN=128: mod 32 == 8 -> conflict-free
#define NS64  72     // B smem stride, BN=64:  mod 32 == 8
#define QS    68     // fused: Q smem stride (68%32==4 -> conflict-free A frags)
#define PS    132    // fused: P smem stride (132%32==4 -> conflict-free A frags)

// Scratch (device globals — no allocation allowed). 336 MB total.
static __device__ float g_q[Mn * Dn];
static __device__ float g_k[Mn * Dn];
static __device__ float g_v[Mn * Dn];
static __device__ float g_p[Mn * Dn];
static __device__ float g_ctx[Mn * Dn];
static __device__ float g_sc[(size_t)BHn * Sn * Sn];

// ---------------------------------------------------------------------------
// fp32 -> packed (bf16 hi | bf16 lo<<16). hi+lo == x to ~2^-18 rel.
// ---------------------------------------------------------------------------
__device__ __forceinline__ unsigned pack_split(float x) {
    __nv_bfloat16 h = __float2bfloat16(x);
    float hf = __bfloat162float(h);
    __nv_bfloat16 l = __float2bfloat16(x - hf);
    return (unsigned)__bfloat16_as_ushort(h) |
           ((unsigned)__bfloat16_as_ushort(l) << 16);
}

__device__ __forceinline__ unsigned swap16(unsigned u) { return (u >> 16) | (u << 16); }

__device__ __forceinline__ void mma_bf16(float c[4], const unsigned a[4],
                                         unsigned b0, unsigned b1) {
    asm volatile(
        "mma.sync.aligned.m16n8k16.row.col.f32.bf16.bf16.f32 "
        "{%0,%1,%2,%3},{%4,%5,%6,%7},{%8,%9},{%0,%1,%2,%3};"
        : "+f"(c[0]), "+f"(c[1]), "+f"(c[2]), "+f"(c[3])
        : "r"(a[0]), "r"(a[1]), "r"(a[2]), "r"(a[3]), "r"(b0), "r"(b1));
}

__device__ __forceinline__ void load8(float v[8], const float* __restrict__ p) {
    float4 a = *reinterpret_cast<const float4*>(p);
    float4 b = *reinterpret_cast<const float4*>(p + 4);
    v[0] = a.x; v[1] = a.y; v[2] = a.z; v[3] = a.w;
    v[4] = b.x; v[5] = b.y; v[6] = b.z; v[7] = b.w;
}

// ---------------------------------------------------------------------------
// Warp compute on one KC=16 stage. Warp tile 64 x (NT*8).
// A: [128][AS] packed (m, real-k). B: [KC][NS] packed (real-k, n).
// Exact fp32 product via dual-mma (normal + half-swapped B).
// ---------------------------------------------------------------------------
template <int NT, int NS>
__device__ __forceinline__ void warp_mma_stage(const unsigned* __restrict__ A,
                                               const unsigned* __restrict__ B,
                                               int wm, int wn, int lane,
                                               float acc[4][NT][4]) {
    const int g = lane >> 2, kq = lane & 3;
    #pragma unroll
    for (int h = 0; h < 2; h++) {          // two m16n8k16 steps = 16 real k
        unsigned af[4][4];
        #pragma unroll
        for (int t = 0; t < 4; t++) {
            const unsigned* p = A + (wm + t * 16 + g) * AS + h * 8 + kq;
            af[t][0] = p[0]; af[t][1] = p[8 * AS];
            af[t][2] = p[4]; af[t][3] = p[8 * AS + 4];
        }
        #pragma unroll
        for (int u = 0; u < NT; u++) {
            const unsigned* q = B + (h * 8 + kq) * NS + wn + u * 8 + g;
            unsigned b0 = q[0], b1 = q[4 * NS];
            unsigned s0 = swap16(b0), s1 = swap16(b1);
            #pragma unroll
            for (int t = 0; t < 4; t++) {
                mma_bf16(acc[t][u], af[t], b0, b1);   // hi*hi + lo*lo
                mma_bf16(acc[t][u], af[t], s0, s1);   // hi*lo + lo*hi
            }
        }
    }
}

// ---------------------------------------------------------------------------
// Projection GEMM: C[8192,512] = X @ W (+bias). 128x128 tile, double-buffered.
// ---------------------------------------------------------------------------
__global__ __launch_bounds__(256, 2) void proj_gemm(const float* __restrict__ X,
                                                    const float* __restrict__ W,
                                                    const float* __restrict__ bias,
                                                    int dst_sel) {
    float* C = (dst_sel == 0) ? g_q : (dst_sel == 1) ? g_k : (dst_sel == 2) ? g_v : g_p;
    __shared__ unsigned Asm[2][128 * AS];
    __shared__ unsigned Bsm[2][KC * NS128];
    const int tid = threadIdx.x, lane = tid & 31, w = tid >> 5;
    const int wm = (w >> 2) * 64, wn = (w & 3) * 32;
    const int mb = blockIdx.y * 128, nb = blockIdx.x * 128;
    const int ar = tid >> 1, akc = (tid & 1) * 8;
    const int br = tid >> 4, bc = (tid & 15) * 8;
    const float* Ag = X + (size_t)(mb + ar) * Dn + akc;
    const float* Bg = W + (size_t)br * Dn + nb + bc;
    float av[8], bv[8];
    load8(av, Ag); load8(bv, Bg);
    float acc[4][4][4] = {};
    int buf = 0;
    for (int k0 = 0; k0 < Dn; k0 += KC) {
        #pragma unroll
        for (int q = 0; q < 8; q++) {
            Asm[buf][ar * AS + akc + q] = pack_split(av[q]);
            Bsm[buf][br * NS128 + bc + q] = pack_split(bv[q]);
        }
        __syncthreads();
        if (k0 + KC < Dn) {
            load8(av, Ag + k0 + KC);
            load8(bv, Bg + (size_t)(k0 + KC) * Dn);
        }
        warp_mma_stage<4, NS128>(Asm[buf], Bsm[buf], wm, wn, lane, acc);
        buf ^= 1;
    }
    const int g = lane >> 2, kq = lane & 3;
    #pragma unroll
    for (int t = 0; t < 4; t++) {
        #pragma unroll
        for (int u = 0; u < 4; u++) {
            const int row = mb + wm + t * 16 + g;
            const int col = nb + wn + u * 8 + 2 * kq;
            float b0 = 0.f, b1 = 0.f;
            if (bias) { b0 = bias[col]; b1 = bias[col + 1]; }
            float2 lo; lo.x = acc[t][u][0] + b0; lo.y = acc[t][u][1] + b1;
            float2 hi; hi.x = acc[t][u][2] + b0; hi.y = acc[t][u][3] + b1;
            *reinterpret_cast<float2*>(C + (size_t)row * Dn + col) = lo;
            *reinterpret_cast<float2*>(C + (size_t)(row + 8) * Dn + col) = hi;
        }
    }
}

// ---------------------------------------------------------------------------
// Output GEMM: out = g_ctx @ Wo + bo.
// ---------------------------------------------------------------------------
__global__ __launch_bounds__(256, 2) void out_gemm(const float* __restrict__ W,
                                                   const float* __restrict__ bias,
                                                   float* __restrict__ C) {
    __shared__ unsigned Asm[2][128 * AS];
    __shared__ unsigned Bsm[2][KC * NS128];
    const int tid = threadIdx.x, lane = tid & 31, w = tid >> 5;
    const int wm = (w >> 2) * 64, wn = (w & 3) * 32;
    const int mb = blockIdx.y * 128, nb = blockIdx.x * 128;
    const int ar = tid >> 1, akc = (tid & 1) * 8;
    const int br = tid >> 4, bc = (tid & 15) * 8;
    const float* Ag = g_ctx + (size_t)(mb + ar) * Dn + akc;
    const float* Bg = W + (size_t)br * Dn + nb + bc;
    float av[8], bv[8];
    load8(av, Ag); load8(bv, Bg);
    float acc[4][4][4] = {};
    int buf = 0;
    for (int k0 = 0; k0 < Dn; k0 += KC) {
        #pragma unroll
        for (int q = 0; q < 8; q++) {
            Asm[buf][ar * AS + akc + q] = pack_split(av[q]);
            Bsm[buf][br * NS128 + bc + q] = pack_split(bv[q]);
        }
        __syncthreads();
        if (k0 + KC < Dn) {
            load8(av, Ag + k0 + KC);
            load8(bv, Bg + (size_t)(k0 + KC) * Dn);
        }
        warp_mma_stage<4, NS128>(Asm[buf], Bsm[buf], wm, wn, lane, acc);
        buf ^= 1;
    }
    const int g = lane >> 2, kq = lane & 3;
    #pragma unroll
    for (int t = 0; t < 4; t++) {
        #pragma unroll
        for (int u = 0; u < 4; u++) {
            const int row = mb + wm + t * 16 + g;
            const int col = nb + wn + u * 8 + 2 * kq;
            const float b0 = bias[col], b1 = bias[col + 1];
            float2 lo; lo.x = acc[t][u][0] + b0; lo.y = acc[t][u][1] + b1;
            float2 hi; hi.x = acc[t][u][2] + b0; hi.y = acc[t][u][3] + b1;
            *reinterpret_cast<float2*>(C + (size_t)row * Dn + col) = lo;
            *reinterpret_cast<float2*>(C + (size_t)(row + 8) * Dn + col) = hi;
        }
    }
}

// ---------------------------------------------------------------------------
// Score pass 0, per (b,h): P[i,c]=(q_i+v_bias).p_c scattered SHIFTED into g_sc:
//   c >= S-1-i -> R[i, c-S+1+i];  c < S-1-i -> R[i-1, c+i+1] (dropped at i==0)
// R[i,i+1] never written (identically 0; masked at read time in attn_fused).
// ---------------------------------------------------------------------------
__global__ __launch_bounds__(256, 2) void score_pos(const float* __restrict__ hb) {
    const int bh = blockIdx.z;
    const int b = bh >> 3, h = bh & 7;
    const int ib = blockIdx.y * 128, jb = blockIdx.x * 128;
    const float* Abase = g_q + (size_t)b * Sn * Dn + h * DHn + (size_t)ib * Dn;
    const float* Bbase = g_p + (size_t)b * Sn * Dn + h * DHn + (size_t)jb * Dn;
    const float* biask = hb + h * DHn;
    __shared__ unsigned Asm[2][128 * AS];
    __shared__ unsigned Bsm[2][KC * NS128];
    const int tid = threadIdx.x, lane = tid & 31, w = tid >> 5;
    const int wm = (w >> 2) * 64, wn = (w & 3) * 32;
    const int ar = tid >> 1, akc = (tid & 1) * 8;
    const float* Ag = Abase + (size_t)ar * Dn + akc;
    const float* Bg = Bbase + (size_t)ar * Dn + akc;   // transposed source
    float av[8], bv[8], bk[8];
    load8(av, Ag); load8(bv, Bg); load8(bk, biask + akc);
    float acc[4][4][4] = {};
    int buf = 0;
    #pragma unroll
    for (int k0 = 0; k0 < DHn; k0 += KC) {
        #pragma unroll
        for (int q = 0; q < 8; q++) {
            Asm[buf][ar * AS + akc + q] = pack_split(av[q] + bk[q]);
            Bsm[buf][(akc + q) * NS128 + ar] = pack_split(bv[q]);
        }
        __syncthreads();
        if (k0 + KC < DHn) {
            load8(av, Ag + k0 + KC);
            load8(bv, Bg + k0 + KC);
            load8(bk, biask + k0 + KC + akc);
        }
        warp_mma_stage<4, NS128>(Asm[buf], Bsm[buf], wm, wn, lane, acc);
        buf ^= 1;
    }
    const size_t base = (size_t)bh * Sn * Sn;
    const int g = lane >> 2, kq = lane & 3;
    #pragma unroll
    for (int t = 0; t < 4; t++) {
        #pragma unroll
        for (int u = 0; u < 4; u++) {
            #pragma unroll
            for (int e = 0; e < 4; e++) {
                const int i = ib + wm + t * 16 + g + (e >= 2 ? 8 : 0);
                const int j = jb + wn + u * 8 + 2 * kq + (e & 1);
                const float val = acc[t][u][e];
                if (j >= Sn - 1 - i)
                    g_sc[base + (size_t)i * Sn + (j - Sn + 1 + i)] = val;
                else if (i > 0)
                    g_sc[base + (size_t)(i - 1) * Sn + (j + i + 1)] = val;
            }
        }
    }
}

// ---------------------------------------------------------------------------
// Fused flash attention: content score (Q+u_bias vs K) + pos bias from g_sc
// + online softmax + P@V, per (b,h, 128-row q strip). 256 threads, 8 warps.
// Dynamic smem: Qsm 128xQS | KVsm union(K 64xNS128, V 128xNS64) | Psm 128xPS
// | redf 4x128 floats.
// ---------------------------------------------------------------------------
#define Q_U32   (128 * QS)                 // 8704
#define KV_U32  (128 * NS64)               // 9216 (>= 64*NS128 = 8704)
#define P_U32   (128 * PS)                 // 16896
#define RED_U32 512
#define FUSED_SMEM_BYTES ((Q_U32 + KV_U32 + P_U32 + RED_U32) * 4)

__global__ __launch_bounds__(256, 1) void attn_fused(const float* __restrict__ ub) {
    extern __shared__ unsigned sm[];
    unsigned* Qsm  = sm;
    unsigned* KVsm = sm + Q_U32;
    unsigned* Psm  = sm + Q_U32 + KV_U32;
    float*    redf = (float*)(sm + Q_U32 + KV_U32 + P_U32);   // [4][128]

    const int bh = blockIdx.y;
    const int b = bh >> 3, h = bh & 7;
    const int ib = blockIdx.x * 128;
    const int tid = threadIdx.x, lane = tid & 31, w = tid >> 5;
    const int g = lane >> 2, kq = lane & 3;
    const int wm = (w >> 2) * 64;
    const int wnS = (w & 3) * 32, wnV = (w & 3) * 16;
    const size_t scbase = (size_t)bh * Sn * Sn;

    // Load Q strip (+u_bias), packed split.
    {
        const int r = tid >> 1, off = (tid & 1) * 32;
        const float* src = g_q + (size_t)(b * Sn + ib + r) * Dn + h * DHn + off;
        const float* bu = ub + h * DHn + off;
        #pragma unroll
        for (int c = 0; c < 32; c += 8) {
            float v[8]; load8(v, src + c);
            #pragma unroll
            for (int q = 0; q < 8; q++)
                Qsm[r * QS + off + c + q] = pack_split(v[q] + bu[c + q]);
        }
    }

    float m_reg[8], lp[8];
    #pragma unroll
    for (int i = 0; i < 8; i++) { m_reg[i] = -1e30f; lp[i] = 0.f; }
    float acc_o[4][2][4] = {};

    for (int jt = 0; jt < 8; jt++) {
        const int j0 = jt * 128;
        __syncthreads();   // prev AV mma done before KVsm overwrite
        // Load K tile transposed: KVsm[k][j], k=0..63, j=0..127, stride NS128.
        {
            const int j = tid >> 1, koff = (tid & 1) * 32;
            const float* src = g_k + (size_t)(b * Sn + j0 + j) * Dn + h * DHn + koff;
            #pragma unroll
            for (int c = 0; c < 32; c += 8) {
                float v[8]; load8(v, src + c);
                #pragma unroll
                for (int q = 0; q < 8; q++)
                    KVsm[(koff + c + q) * NS128 + j] = pack_split(v[q]);
            }
        }
        __syncthreads();
        // Content score mma: 64 real k = 8 h-steps.
        float acc_s[4][4][4] = {};
        #pragma unroll
        for (int hh = 0; hh < 8; hh++) {
            unsigned af[4][4];
            #pragma unroll
            for (int t = 0; t < 4; t++) {
                const unsigned* p = Qsm + (wm + t * 16 + g) * QS + hh * 8 + kq;
                af[t][0] = p[0]; af[t][1] = p[8 * QS];
                af[t][2] = p[4]; af[t][3] = p[8 * QS + 4];
            }
            #pragma unroll
            for (int u = 0; u < 4; u++) {
                const unsigned* q = KVsm + (hh * 8 + kq) * NS128 + wnS + u * 8 + g;
                unsigned b0 = q[0], b1 = q[4 * NS128];
                unsigned s0 = swap16(b0), s1 = swap16(b1);
                #pragma unroll
                for (int t = 0; t < 4; t++) {
                    mma_bf16(acc_s[t][u], af[t], b0, b1);
                    mma_bf16(acc_s[t][u], af[t], s0, s1);
                }
            }
        }
        // Add pos bias (pre-shifted in g_sc; j==i+1 slot is 0), scale, row max.
        float pm[8];
        #pragma unroll
        for (int i = 0; i < 8; i++) pm[i] = -1e30f;
        #pragma unroll
        for (int t = 0; t < 4; t++) {
            #pragma unroll
            for (int rh = 0; rh < 2; rh++) {
                const int i = ib + wm + t * 16 + g + rh * 8;
                const float* row = g_sc + scbase + (size_t)i * Sn + j0;
                const int idx = t * 2 + rh;
                #pragma unroll
                for (int u = 0; u < 4; u++) {
                    const int jl = wnS + u * 8 + 2 * kq;
                    float2 pv = *reinterpret_cast<const float2*>(row + jl);
                    const int jg = j0 + jl;
                    float p0 = (jg == i + 1) ? 0.f : pv.x;
                    float p1 = (jg + 1 == i + 1) ? 0.f : pv.y;
                    float s0v = (acc_s[t][u][rh * 2 + 0] + p0) * SCALE;
                    float s1v = (acc_s[t][u][rh * 2 + 1] + p1) * SCALE;
                    acc_s[t][u][rh * 2 + 0] = s0v;
                    acc_s[t][u][rh * 2 + 1] = s1v;
                    pm[idx] = fmaxf(pm[idx], fmaxf(s0v, s1v));
                }
            }
        }
        // Row max across kq lanes, then across the 4 n-warps via smem.
        #pragma unroll
        for (int i = 0; i < 8; i++) {
            pm[i] = fmaxf(pm[i], __shfl_xor_sync(0xffffffffu, pm[i], 1));
            pm[i] = fmaxf(pm[i], __shfl_xor_sync(0xffffffffu, pm[i], 2));
        }
        if (kq == 0) {
            #pragma unroll
            for (int t = 0; t < 4; t++)
                #pragma unroll
                for (int rh = 0; rh < 2; rh++)
                    redf[(w & 3) * 128 + wm + t * 16 + g + rh * 8] = pm[t * 2 + rh];
        }
        __syncthreads();
        float alpha[8];
        #pragma unroll
        for (int t = 0; t < 4; t++) {
            #pragma unroll
            for (int rh = 0; rh < 2; rh++) {
                const int r = wm + t * 16 + g + rh * 8, idx = t * 2 + rh;
                float tm = fmaxf(fmaxf(redf[r], redf[128 + r]),
                                 fmaxf(redf[256 + r], redf[384 + r]));
                float mn = fmaxf(m_reg[idx], tm);
                alpha[idx] = __expf(m_reg[idx] - mn);
                m_reg[idx] = mn;
                lp[idx] *= alpha[idx];
            }
        }
        #pragma unroll
        for (int t = 0; t < 4; t++)
            #pragma unroll
            for (int u = 0; u < 2; u++) {
                acc_o[t][u][0] *= alpha[t * 2];     acc_o[t][u][1] *= alpha[t * 2];
                acc_o[t][u][2] *= alpha[t * 2 + 1]; acc_o[t][u][3] *= alpha[t * 2 + 1];
            }
        // P = exp(s - m); accumulate partial row sums; pack into Psm.
        #pragma unroll
        for (int t = 0; t < 4; t++) {
            #pragma unroll
            for (int rh = 0; rh < 2; rh++) {
                const int idx = t * 2 + rh;
                const int rloc = wm + t * 16 + g + rh * 8;
                #pragma unroll
                for (int u = 0; u < 4; u++) {
                    const int jl = wnS + u * 8 + 2 * kq;
                    float p0 = __expf(acc_s[t][u][rh * 2 + 0] - m_reg[idx]);
                    float p1 = __expf(acc_s[t][u][rh * 2 + 1] - m_reg[idx]);
                    lp[idx] += p0 + p1;
                    Psm[rloc * PS + jl] = pack_split(p0);
                    Psm[rloc * PS + jl + 1] = pack_split(p1);
                }
            }
        }
        __syncthreads();   // Psm ready; K reads done -> reuse KVsm for V
        // Load V tile: KVsm[j][d], stride NS64.
        {
            const int j = tid >> 1, off = (tid & 1) * 32;
            const float* src = g_v + (size_t)(b * Sn + j0 + j) * Dn + h * DHn + off;
            #pragma unroll
            for (int c = 0; c < 32; c += 8) {
                float v[8]; load8(v, src + c);
                #pragma unroll
                for (int q = 0; q < 8; q++)
                    KVsm[j * NS64 + off + c + q] = pack_split(v[q]);
            }
        }
        __syncthreads();
        // AV mma: 128 real k = 16 h-steps, NT=2 (64 cols / 4 warps).
        #pragma unroll
        for (int hh = 0; hh < 16; hh++) {
            unsigned af[4][4];
            #pragma unroll
            for (int t = 0; t < 4; t++) {
                const unsigned* p = Psm + (wm + t * 16 + g) * PS + hh * 8 + kq;
                af[t][0] = p[0]; af[t][1] = p[8 * PS];
                af[t][2] = p[4]; af[t][3] = p[8 * PS + 4];
            }
            #pragma unroll
            for (int u = 0; u < 2; u++) {
                const unsigned* q = KVsm + (hh * 8 + kq) * NS64 + wnV + u * 8 + g;
                unsigned b0 = q[0], b1 = q[4 * NS64];
                unsigned s0 = swap16(b0), s1 = swap16(b1);
                #pragma unroll
                for (int t = 0; t < 4; t++) {
                    mma_bf16(acc_o[t][u], af[t], b0, b1);
                    mma_bf16(acc_o[t][u], af[t], s0, s1);
                }
            }
        }
    }
    // Final row-sum reduction and normalized output.
    #pragma unroll
    for (int i = 0; i < 8; i++) {
        lp[i] += __shfl_xor_sync(0xffffffffu, lp[i], 1);
        lp[i] += __shfl_xor_sync(0xffffffffu, lp[i], 2);
    }
    __syncthreads();
    if (kq == 0) {
        #pragma unroll
        for (int t = 0; t < 4; t++)
            #pragma unroll
            for (int rh = 0; rh < 2; rh++)
                redf[(w & 3) * 128 + wm + t * 16 + g + rh * 8] = lp[t * 2 + rh];
    }
    __syncthreads();
    float inv[8];
    #pragma unroll
    for (int t = 0; t < 4; t++) {
        #pragma unroll
        for (int rh = 0; rh < 2; rh++) {
            const int r = wm + t * 16 + g + rh * 8;
            inv[t * 2 + rh] = 1.0f / (redf[r] + redf[128 + r] + redf[256 + r] + redf[384 + r]);
        }
    }
    #pragma unroll
    for (int t = 0; t < 4; t++) {
        #pragma unroll
        for (int u = 0; u < 2; u++) {
            const int i = ib + wm + t * 16 + g;
            const int col = h * DHn + wnV + u * 8 + 2 * kq;
            float2 lo; lo.x = acc_o[t][u][0] * inv[t * 2];     lo.y = acc_o[t][u][1] * inv[t * 2];
            float2 hi; hi.x = acc_o[t][u][2] * inv[t * 2 + 1]; hi.y = acc_o[t][u][3] * inv[t * 2 + 1];
            *reinterpret_cast<float2*>(g_ctx + (size_t)(b * Sn + i) * Dn + col) = lo;
            *reinterpret_cast<float2*>(g_ctx + (size_t)(b * Sn + i + 8) * Dn + col) = hi;
        }
    }
}

// ---------------------------------------------------------------------------
extern "C" void kernel_launch(void* const* d_in, const int* in_sizes, int n_in,
                              void* d_out, int out_size) {
    (void)in_sizes; (void)n_in; (void)out_size;
    const float* query = (const float*)d_in[0];
    const float* key   = (const float*)d_in[1];
    const float* value = (const float*)d_in[2];
    const float* pemb  = (const float*)d_in[3];
    const float* Wq    = (const float*)d_in[4];
    const float* bq    = (const float*)d_in[5];
    const float* Wk    = (const float*)d_in[6];
    const float* bk    = (const float*)d_in[7];
    const float* Wv    = (const float*)d_in[8];
    const float* bv    = (const float*)d_in[9];
    const float* Wp    = (const float*)d_in[10];
    const float* u_bias = (const float*)d_in[11];
    const float* v_bias = (const float*)d_in[12];
    const float* Wo    = (const float*)d_in[13];
    const float* bo    = (const float*)d_in[14];
    float* out = (float*)d_out;

    cudaFuncSetAttribute(attn_fused, cudaFuncAttributeMaxDynamicSharedMemorySize,
                         FUSED_SMEM_BYTES);

    dim3 gproj(Dn / 128, Mn / 128);       // (4, 64)
    proj_gemm<<<gproj, 256>>>(query, Wq, bq, 0);
    proj_gemm<<<gproj, 256>>>(key,   Wk, bk, 1);
    proj_gemm<<<gproj, 256>>>(value, Wv, bv, 2);
    proj_gemm<<<gproj, 256>>>(pemb,  Wp, nullptr, 3);

    dim3 gsc(Sn / 128, Sn / 128, BHn);    // (8, 8, 64)
    score_pos<<<gsc, 256>>>(v_bias);      // pos scores scattered (shifted) -> g_sc

    dim3 gf(Sn / 128, BHn);               // (8, 64)
    attn_fused<<<gf, 256, FUSED_SMEM_BYTES>>>(u_bias);

    out_gemm<<<gproj, 256>>>(Wo, bo, out);
}

// round 10
// speedup vs baseline: 2.1822x; 1.0282x over previous
#include <cuda_runtime.h>
#include <cuda_bf16.h>

// Problem constants
#define Bn   8
#define Sn   1024
#define Dn   512
#define Hn   8
#define DHn  64
#define BHn  (Bn * Hn)      // 64
#define Mn   (Bn * Sn)      // 8192
#define SCALE 0.044194173824159216f   // 1/sqrt(512)

#define KC    16     // real-k per smem stage (GEMM kernels)
#define AS    20     // A smem stride (u32): conflict-free frags
#define NS128 136    // B smem stride, BN=128: mod 32 == 8 -> conflict-free
#define NS64  72     // B smem stride, BN=64:  mod 32 == 8
#define QS    68     // fused: Q smem stride
#define PS    132    // fused: P smem stride

// Scratch (device globals — no allocation allowed). ~357 MB total.
// All activation tensors stored PRE-PACKED as (bf16 hi | bf16 lo<<16) u32.
static __device__ unsigned g_qu[Mn * Dn];   // pack(SCALE*(q + bq + u_bias))
static __device__ unsigned g_qv[Mn * Dn];   // pack(SCALE*(q + bq + v_bias))
static __device__ unsigned g_k[Mn * Dn];
static __device__ unsigned g_v[Mn * Dn];
static __device__ unsigned g_p[Mn * Dn];
static __device__ unsigned g_ctx[Mn * Dn];
static __device__ float    g_sc[(size_t)BHn * Sn * Sn];  // pre-scaled shifted pos
// Packed weights
static __device__ unsigned g_wq[Dn * Dn];
static __device__ unsigned g_wk[Dn * Dn];
static __device__ unsigned g_wv[Dn * Dn];
static __device__ unsigned g_wp[Dn * Dn];
static __device__ unsigned g_wo[Dn * Dn];

// ---------------------------------------------------------------------------
__device__ __forceinline__ unsigned pack_split(float x) {
    __nv_bfloat16 h = __float2bfloat16(x);
    float hf = __bfloat162float(h);
    __nv_bfloat16 l = __float2bfloat16(x - hf);
    return (unsigned)__bfloat16_as_ushort(h) |
           ((unsigned)__bfloat16_as_ushort(l) << 16);
}

__device__ __forceinline__ unsigned swap16(unsigned u) { return (u >> 16) | (u << 16); }

__device__ __forceinline__ void mma_bf16(float c[4], const unsigned a[4],
                                         unsigned b0, unsigned b1) {
    asm volatile(
        "mma.sync.aligned.m16n8k16.row.col.f32.bf16.bf16.f32 "
        "{%0,%1,%2,%3},{%4,%5,%6,%7},{%8,%9},{%0,%1,%2,%3};"
        : "+f"(c[0]), "+f"(c[1]), "+f"(c[2]), "+f"(c[3])
        : "r"(a[0]), "r"(a[1]), "r"(a[2]), "r"(a[3]), "r"(b0), "r"(b1));
}

__device__ __forceinline__ void load8f(float v[8], const float* __restrict__ p) {
    float4 a = *reinterpret_cast<const float4*>(p);
    float4 b = *reinterpret_cast<const float4*>(p + 4);
    v[0] = a.x; v[1] = a.y; v[2] = a.z; v[3] = a.w;
    v[4] = b.x; v[5] = b.y; v[6] = b.z; v[7] = b.w;
}

__device__ __forceinline__ void load8u(unsigned v[8], const unsigned* __restrict__ p) {
    uint4 a = *reinterpret_cast<const uint4*>(p);
    uint4 b = *reinterpret_cast<const uint4*>(p + 4);
    v[0] = a.x; v[1] = a.y; v[2] = a.z; v[3] = a.w;
    v[4] = b.x; v[5] = b.y; v[6] = b.z; v[7] = b.w;
}

// ---------------------------------------------------------------------------
// Weight pack kernel: fp32 -> packed u32, one element per thread.
// ---------------------------------------------------------------------------
__global__ void pack_w(const float* __restrict__ src, int sel) {
    unsigned* dst = (sel == 0) ? g_wq : (sel == 1) ? g_wk : (sel == 2) ? g_wv
                  : (sel == 3) ? g_wp : g_wo;
    const int i = blockIdx.x * 256 + threadIdx.x;
    dst[i] = pack_split(src[i]);
}

// ---------------------------------------------------------------------------
// Warp compute on one KC=16 stage. Warp tile 64 x (NT*8).
// ---------------------------------------------------------------------------
template <int NT, int NS>
__device__ __forceinline__ void warp_mma_stage(const unsigned* __restrict__ A,
                                               const unsigned* __restrict__ B,
                                               int wm, int wn, int lane,
                                               float acc[4][NT][4]) {
    const int g = lane >> 2, kq = lane & 3;
    #pragma unroll
    for (int h = 0; h < 2; h++) {
        unsigned af[4][4];
        #pragma unroll
        for (int t = 0; t < 4; t++) {
            const unsigned* p = A + (wm + t * 16 + g) * AS + h * 8 + kq;
            af[t][0] = p[0]; af[t][1] = p[8 * AS];
            af[t][2] = p[4]; af[t][3] = p[8 * AS + 4];
        }
        #pragma unroll
        for (int u = 0; u < NT; u++) {
            const unsigned* q = B + (h * 8 + kq) * NS + wn + u * 8 + g;
            unsigned b0 = q[0], b1 = q[4 * NS];
            unsigned s0 = swap16(b0), s1 = swap16(b1);
            #pragma unroll
            for (int t = 0; t < 4; t++) {
                mma_bf16(acc[t][u], af[t], b0, b1);   // hi*hi + lo*lo
                mma_bf16(acc[t][u], af[t], s0, s1);   // hi*lo + lo*hi
            }
        }
    }
}

// ---------------------------------------------------------------------------
// Projection GEMM: C = X @ W (+bias). 128x128 tile, double-buffered.
// dst_sel: 0=Q (writes g_qu & g_qv with SCALE and u/v bias), 1=K, 2=V, 3=P.
// B operand comes pre-packed; outputs stored packed.
// ---------------------------------------------------------------------------
__global__ __launch_bounds__(256, 2) void proj_gemm(const float* __restrict__ X,
                                                    const unsigned* __restrict__ Wpk,
                                                    const float* __restrict__ bias,
                                                    const float* __restrict__ ub,
                                                    const float* __restrict__ vb,
                                                    int dst_sel) {
    __shared__ unsigned Asm[2][128 * AS];
    __shared__ unsigned Bsm[2][KC * NS128];
    const int tid = threadIdx.x, lane = tid & 31, w = tid >> 5;
    const int wm = (w >> 2) * 64, wn = (w & 3) * 32;
    const int mb = blockIdx.y * 128, nb = blockIdx.x * 128;
    const int ar = tid >> 1, akc = (tid & 1) * 8;
    const int br = tid >> 4, bc = (tid & 15) * 8;
    const float* Ag = X + (size_t)(mb + ar) * Dn + akc;
    const unsigned* Bg = Wpk + (size_t)br * Dn + nb + bc;
    float av[8]; unsigned bv[8];
    load8f(av, Ag); load8u(bv, Bg);
    float acc[4][4][4] = {};
    int buf = 0;
    for (int k0 = 0; k0 < Dn; k0 += KC) {
        #pragma unroll
        for (int q = 0; q < 8; q++) {
            Asm[buf][ar * AS + akc + q] = pack_split(av[q]);
            Bsm[buf][br * NS128 + bc + q] = bv[q];
        }
        __syncthreads();
        if (k0 + KC < Dn) {
            load8f(av, Ag + k0 + KC);
            load8u(bv, Bg + (size_t)(k0 + KC) * Dn);
        }
        warp_mma_stage<4, NS128>(Asm[buf], Bsm[buf], wm, wn, lane, acc);
        buf ^= 1;
    }
    const int g = lane >> 2, kq = lane & 3;
    #pragma unroll
    for (int t = 0; t < 4; t++) {
        #pragma unroll
        for (int u = 0; u < 4; u++) {
            #pragma unroll
            for (int e = 0; e < 4; e++) {
                const int row = mb + wm + t * 16 + g + (e >= 2 ? 8 : 0);
                const int col = nb + wn + u * 8 + 2 * kq + (e & 1);
                const size_t idx = (size_t)row * Dn + col;
                float r = acc[t][u][e];
                if (bias) r += bias[col];
                if (dst_sel == 0) {
                    g_qu[idx] = pack_split(SCALE * (r + ub[col]));
                    g_qv[idx] = pack_split(SCALE * (r + vb[col]));
                } else if (dst_sel == 1) g_k[idx] = pack_split(r);
                else if (dst_sel == 2)   g_v[idx] = pack_split(r);
                else                     g_p[idx] = pack_split(r);
            }
        }
    }
}

// ---------------------------------------------------------------------------
// Output GEMM: out = unpack(g_ctx) @ Wo + bo. Both operands pre-packed.
// ---------------------------------------------------------------------------
__global__ __launch_bounds__(256, 2) void out_gemm(const float* __restrict__ bias,
                                                   float* __restrict__ C) {
    __shared__ unsigned Asm[2][128 * AS];
    __shared__ unsigned Bsm[2][KC * NS128];
    const int tid = threadIdx.x, lane = tid & 31, w = tid >> 5;
    const int wm = (w >> 2) * 64, wn = (w & 3) * 32;
    const int mb = blockIdx.y * 128, nb = blockIdx.x * 128;
    const int ar = tid >> 1, akc = (tid & 1) * 8;
    const int br = tid >> 4, bc = (tid & 15) * 8;
    const unsigned* Ag = g_ctx + (size_t)(mb + ar) * Dn + akc;
    const unsigned* Bg = g_wo + (size_t)br * Dn + nb + bc;
    unsigned av[8], bv[8];
    load8u(av, Ag); load8u(bv, Bg);
    float acc[4][4][4] = {};
    int buf = 0;
    for (int k0 = 0; k0 < Dn; k0 += KC) {
        #pragma unroll
        for (int q = 0; q < 8; q++) {
            Asm[buf][ar * AS + akc + q] = av[q];
            Bsm[buf][br * NS128 + bc + q] = bv[q];
        }
        __syncthreads();
        if (k0 + KC < Dn) {
            load8u(av, Ag + k0 + KC);
            load8u(bv, Bg + (size_t)(k0 + KC) * Dn);
        }
        warp_mma_stage<4, NS128>(Asm[buf], Bsm[buf], wm, wn, lane, acc);
        buf ^= 1;
    }
    const int g = lane >> 2, kq = lane & 3;
    #pragma unroll
    for (int t = 0; t < 4; t++) {
        #pragma unroll
        for (int u = 0; u < 4; u++) {
            const int row = mb + wm + t * 16 + g;
            const int col = nb + wn + u * 8 + 2 * kq;
            const float b0 = bias[col], b1 = bias[col + 1];
            float2 lo; lo.x = acc[t][u][0] + b0; lo.y = acc[t][u][1] + b1;
            float2 hi; hi.x = acc[t][u][2] + b0; hi.y = acc[t][u][3] + b1;
            *reinterpret_cast<float2*>(C + (size_t)row * Dn + col) = lo;
            *reinterpret_cast<float2*>(C + (size_t)(row + 8) * Dn + col) = hi;
        }
    }
}

// ---------------------------------------------------------------------------
// Score pass 0, per (b,h): P[i,c]=SCALE*(q_i+vb).p_c (scale pre-folded into
// g_qv) scattered SHIFTED into g_sc:
//   c >= S-1-i -> R[i, c-S+1+i];  c < S-1-i -> R[i-1, c+i+1] (dropped at i==0)
// R[i,i+1] never written (identically 0; masked at read time in attn_fused).
// Operands pre-packed: loaders are pure u32 copies.
// ---------------------------------------------------------------------------
__global__ __launch_bounds__(256, 2) void score_pos() {
    const int bh = blockIdx.z;
    const int b = bh >> 3, h = bh & 7;
    const int ib = blockIdx.y * 128, jb = blockIdx.x * 128;
    const unsigned* Ag = g_qv + (size_t)(b * Sn + ib) * Dn + h * DHn;
    const unsigned* Bg = g_p + (size_t)(b * Sn + jb) * Dn + h * DHn;
    __shared__ unsigned Asm[2][128 * AS];
    __shared__ unsigned Bsm[2][KC * NS128];
    const int tid = threadIdx.x, lane = tid & 31, w = tid >> 5;
    const int wm = (w >> 2) * 64, wn = (w & 3) * 32;
    const int ar = tid >> 1, akc = (tid & 1) * 8;
    const unsigned* Agr = Ag + (size_t)ar * Dn + akc;
    const unsigned* Bgr = Bg + (size_t)ar * Dn + akc;   // transposed source
    unsigned av[8], bv[8];
    load8u(av, Agr); load8u(bv, Bgr);
    float acc[4][4][4] = {};
    int buf = 0;
    #pragma unroll
    for (int k0 = 0; k0 < DHn; k0 += KC) {
        #pragma unroll
        for (int q = 0; q < 8; q++) {
            Asm[buf][ar * AS + akc + q] = av[q];
            Bsm[buf][(akc + q) * NS128 + ar] = bv[q];
        }
        __syncthreads();
        if (k0 + KC < DHn) {
            load8u(av, Agr + k0 + KC);
            load8u(bv, Bgr + k0 + KC);
        }
        warp_mma_stage<4, NS128>(Asm[buf], Bsm[buf], wm, wn, lane, acc);
        buf ^= 1;
    }
    const size_t base = (size_t)bh * Sn * Sn;
    const int g = lane >> 2, kq = lane & 3;
    #pragma unroll
    for (int t = 0; t < 4; t++) {
        #pragma unroll
        for (int u = 0; u < 4; u++) {
            #pragma unroll
            for (int e = 0; e < 4; e++) {
                const int i = ib + wm + t * 16 + g + (e >= 2 ? 8 : 0);
                const int j = jb + wn + u * 8 + 2 * kq + (e & 1);
                const float val = acc[t][u][e];
                if (j >= Sn - 1 - i)
                    g_sc[base + (size_t)i * Sn + (j - Sn + 1 + i)] = val;
                else if (i > 0)
                    g_sc[base + (size_t)(i - 1) * Sn + (j + i + 1)] = val;
            }
        }
    }
}

// ---------------------------------------------------------------------------
// Fused flash attention: content score (g_qu vs g_k, both pre-scaled/packed)
// + pos bias from g_sc (pre-scaled) + online softmax + P@V.
// Per (b,h, 128-row q strip). 256 threads, 8 warps. Writes g_ctx packed.
// ---------------------------------------------------------------------------
#define Q_U32   (128 * QS)
#define KV_U32  (128 * NS64)
#define P_U32   (128 * PS)
#define RED_U32 512
#define FUSED_SMEM_BYTES ((Q_U32 + KV_U32 + P_U32 + RED_U32) * 4)

__global__ __launch_bounds__(256, 1) void attn_fused() {
    extern __shared__ unsigned sm[];
    unsigned* Qsm  = sm;
    unsigned* KVsm = sm + Q_U32;
    unsigned* Psm  = sm + Q_U32 + KV_U32;
    float*    redf = (float*)(sm + Q_U32 + KV_U32 + P_U32);   // [4][128]

    const int bh = blockIdx.y;
    const int b = bh >> 3, h = bh & 7;
    const int ib = blockIdx.x * 128;
    const int tid = threadIdx.x, lane = tid & 31, w = tid >> 5;
    const int g = lane >> 2, kq = lane & 3;
    const int wm = (w >> 2) * 64;
    const int wnS = (w & 3) * 32, wnV = (w & 3) * 16;
    const size_t scbase = (size_t)bh * Sn * Sn;

    // Load Q strip (pre-packed, pre-scaled, u_bias folded).
    {
        const int r = tid >> 1, off = (tid & 1) * 32;
        const unsigned* src = g_qu + (size_t)(b * Sn + ib + r) * Dn + h * DHn + off;
        #pragma unroll
        for (int c = 0; c < 32; c += 8) {
            unsigned v[8]; load8u(v, src + c);
            #pragma unroll
            for (int q = 0; q < 8; q++) Qsm[r * QS + off + c + q] = v[q];
        }
    }

    float m_reg[8], lp[8];
    #pragma unroll
    for (int i = 0; i < 8; i++) { m_reg[i] = -1e30f; lp[i] = 0.f; }
    float acc_o[4][2][4] = {};

    for (int jt = 0; jt < 8; jt++) {
        const int j0 = jt * 128;
        __syncthreads();   // prev AV mma done before KVsm overwrite
        // K tile transposed copy: KVsm[k][j], stride NS128.
        {
            const int j = tid >> 1, koff = (tid & 1) * 32;
            const unsigned* src = g_k + (size_t)(b * Sn + j0 + j) * Dn + h * DHn + koff;
            #pragma unroll
            for (int c = 0; c < 32; c += 8) {
                unsigned v[8]; load8u(v, src + c);
                #pragma unroll
                for (int q = 0; q < 8; q++) KVsm[(koff + c + q) * NS128 + j] = v[q];
            }
        }
        __syncthreads();
        // Content score mma: 64 real k = 8 h-steps (result pre-scaled).
        float acc_s[4][4][4] = {};
        #pragma unroll
        for (int hh = 0; hh < 8; hh++) {
            unsigned af[4][4];
            #pragma unroll
            for (int t = 0; t < 4; t++) {
                const unsigned* p = Qsm + (wm + t * 16 + g) * QS + hh * 8 + kq;
                af[t][0] = p[0]; af[t][1] = p[8 * QS];
                af[t][2] = p[4]; af[t][3] = p[8 * QS + 4];
            }
            #pragma unroll
            for (int u = 0; u < 4; u++) {
                const unsigned* q = KVsm + (hh * 8 + kq) * NS128 + wnS + u * 8 + g;
                unsigned b0 = q[0], b1 = q[4 * NS128];
                unsigned s0 = swap16(b0), s1 = swap16(b1);
                #pragma unroll
                for (int t = 0; t < 4; t++) {
                    mma_bf16(acc_s[t][u], af[t], b0, b1);
                    mma_bf16(acc_s[t][u], af[t], s0, s1);
                }
            }
        }
        // Add pre-scaled pos bias (j==i+1 slot forced to 0), row max.
        float pm[8];
        #pragma unroll
        for (int i = 0; i < 8; i++) pm[i] = -1e30f;
        #pragma unroll
        for (int t = 0; t < 4; t++) {
            #pragma unroll
            for (int rh = 0; rh < 2; rh++) {
                const int i = ib + wm + t * 16 + g + rh * 8;
                const float* row = g_sc + scbase + (size_t)i * Sn + j0;
                const int idx = t * 2 + rh;
                #pragma unroll
                for (int u = 0; u < 4; u++) {
                    const int jl = wnS + u * 8 + 2 * kq;
                    float2 pv = *reinterpret_cast<const float2*>(row + jl);
                    const int jg = j0 + jl;
                    float p0 = (jg == i + 1) ? 0.f : pv.x;
                    float p1 = (jg + 1 == i + 1) ? 0.f : pv.y;
                    float s0v = acc_s[t][u][rh * 2 + 0] + p0;
                    float s1v = acc_s[t][u][rh * 2 + 1] + p1;
                    acc_s[t][u][rh * 2 + 0] = s0v;
                    acc_s[t][u][rh * 2 + 1] = s1v;
                    pm[idx] = fmaxf(pm[idx], fmaxf(s0v, s1v));
                }
            }
        }
        #pragma unroll
        for (int i = 0; i < 8; i++) {
            pm[i] = fmaxf(pm[i], __shfl_xor_sync(0xffffffffu, pm[i], 1));
            pm[i] = fmaxf(pm[i], __shfl_xor_sync(0xffffffffu, pm[i], 2));
        }
        if (kq == 0) {
            #pragma unroll
            for (int t = 0; t < 4; t++)
                #pragma unroll
                for (int rh = 0; rh < 2; rh++)
                    redf[(w & 3) * 128 + wm + t * 16 + g + rh * 8] = pm[t * 2 + rh];
        }
        __syncthreads();
        float alpha[8];
        #pragma unroll
        for (int t = 0; t < 4; t++) {
            #pragma unroll
            for (int rh = 0; rh < 2; rh++) {
                const int r = wm + t * 16 + g + rh * 8, idx = t * 2 + rh;
                float tm = fmaxf(fmaxf(redf[r], redf[128 + r]),
                                 fmaxf(redf[256 + r], redf[384 + r]));
                float mn = fmaxf(m_reg[idx], tm);
                alpha[idx] = __expf(m_reg[idx] - mn);
                m_reg[idx] = mn;
                lp[idx] *= alpha[idx];
            }
        }
        #pragma unroll
        for (int t = 0; t < 4; t++)
            #pragma unroll
            for (int u = 0; u < 2; u++) {
                acc_o[t][u][0] *= alpha[t * 2];     acc_o[t][u][1] *= alpha[t * 2];
                acc_o[t][u][2] *= alpha[t * 2 + 1]; acc_o[t][u][3] *= alpha[t * 2 + 1];
            }
        // P = exp(s - m); partial row sums; pack into Psm.
        #pragma unroll
        for (int t = 0; t < 4; t++) {
            #pragma unroll
            for (int rh = 0; rh < 2; rh++) {
                const int idx = t * 2 + rh;
                const int rloc = wm + t * 16 + g + rh * 8;
                #pragma unroll
                for (int u = 0; u < 4; u++) {
                    const int jl = wnS + u * 8 + 2 * kq;
                    float p0 = __expf(acc_s[t][u][rh * 2 + 0] - m_reg[idx]);
                    float p1 = __expf(acc_s[t][u][rh * 2 + 1] - m_reg[idx]);
                    lp[idx] += p0 + p1;
                    Psm[rloc * PS + jl] = pack_split(p0);
                    Psm[rloc * PS + jl + 1] = pack_split(p1);
                }
            }
        }
        __syncthreads();   // Psm ready; K reads done -> reuse KVsm for V
        // V tile copy: KVsm[j][d], stride NS64.
        {
            const int j = tid >> 1, off = (tid & 1) * 32;
            const unsigned* src = g_v + (size_t)(b * Sn + j0 + j) * Dn + h * DHn + off;
            #pragma unroll
            for (int c = 0; c < 32; c += 8) {
                unsigned v[8]; load8u(v, src + c);
                #pragma unroll
                for (int q = 0; q < 8; q++) KVsm[j * NS64 + off + c + q] = v[q];
            }
        }
        __syncthreads();
        // AV mma: 128 real k = 16 h-steps, NT=2.
        #pragma unroll
        for (int hh = 0; hh < 16; hh++) {
            unsigned af[4][4];
            #pragma unroll
            for (int t = 0; t < 4; t++) {
                const unsigned* p = Psm + (wm + t * 16 + g) * PS + hh * 8 + kq;
                af[t][0] = p[0]; af[t][1] = p[8 * PS];
                af[t][2] = p[4]; af[t][3] = p[8 * PS + 4];
            }
            #pragma unroll
            for (int u = 0; u < 2; u++) {
                const unsigned* q = KVsm + (hh * 8 + kq) * NS64 + wnV + u * 8 + g;
                unsigned b0 = q[0], b1 = q[4 * NS64];
                unsigned s0 = swap16(b0), s1 = swap16(b1);
                #pragma unroll
                for (int t = 0; t < 4; t++) {
                    mma_bf16(acc_o[t][u], af[t], b0, b1);
                    mma_bf16(acc_o[t][u], af[t], s0, s1);
                }
            }
        }
    }
    // Final row-sum reduction and normalized packed output.
    #pragma unroll
    for (int i = 0; i < 8; i++) {
        lp[i] += __shfl_xor_sync(0xffffffffu, lp[i], 1);
        lp[i] += __shfl_xor_sync(0xffffffffu, lp[i], 2);
    }
    __syncthreads();
    if (kq == 0) {
        #pragma unroll
        for (int t = 0; t < 4; t++)
            #pragma unroll
            for (int rh = 0; rh < 2; rh++)
                redf[(w & 3) * 128 + wm + t * 16 + g + rh * 8] = lp[t * 2 + rh];
    }
    __syncthreads();
    float inv[8];
    #pragma unroll
    for (int t = 0; t < 4; t++) {
        #pragma unroll
        for (int rh = 0; rh < 2; rh++) {
            const int r = wm + t * 16 + g + rh * 8;
            inv[t * 2 + rh] = 1.0f / (redf[r] + redf[128 + r] + redf[256 + r] + redf[384 + r]);
        }
    }
    #pragma unroll
    for (int t = 0; t < 4; t++) {
        #pragma unroll
        for (int u = 0; u < 2; u++) {
            #pragma unroll
            for (int e = 0; e < 4; e++) {
                const int i = ib + wm + t * 16 + g + (e >= 2 ? 8 : 0);
                const int col = h * DHn + wnV + u * 8 + 2 * kq + (e & 1);
                g_ctx[(size_t)(b * Sn + i) * Dn + col] =
                    pack_split(acc_o[t][u][e] * inv[t * 2 + (e >= 2 ? 1 : 0)]);
            }
        }
    }
}

// ---------------------------------------------------------------------------
extern "C" void kernel_launch(void* const* d_in, const int* in_sizes, int n_in,
                              void* d_out, int out_size) {
    (void)in_sizes; (void)n_in; (void)out_size;
    const float* query = (const float*)d_in[0];
    const float* key   = (const float*)d_in[1];
    const float* value = (const float*)d_in[2];
    const float* pemb  = (const float*)d_in[3];
    const float* Wq    = (const float*)d_in[4];
    const float* bq    = (const float*)d_in[5];
    const float* Wk    = (const float*)d_in[6];
    const float* bk    = (const float*)d_in[7];
    const float* Wv    = (const float*)d_in[8];
    const float* bv    = (const float*)d_in[9];
    const float* Wp    = (const float*)d_in[10];
    const float* u_bias = (const float*)d_in[11];
    const float* v_bias = (const float*)d_in[12];
    const float* Wo    = (const float*)d_in[13];
    const float* bo    = (const float*)d_in[14];
    float* out = (float*)d_out;

    cudaFuncSetAttribute(attn_fused, cudaFuncAttributeMaxDynamicSharedMemorySize,
                         FUSED_SMEM_BYTES);

    // Pack weights (u32 split form), once per launch.
    pack_w<<<Dn * Dn / 256, 256>>>(Wq, 0);
    pack_w<<<Dn * Dn / 256, 256>>>(Wk, 1);
    pack_w<<<Dn * Dn / 256, 256>>>(Wv, 2);
    pack_w<<<Dn * Dn / 256, 256>>>(Wp, 3);
    pack_w<<<Dn * Dn / 256, 256>>>(Wo, 4);

    // Resolve packed weight device addresses once (static, idempotent).
    static unsigned *wq_p = nullptr, *wk_p = nullptr, *wv_p = nullptr, *wp_p = nullptr;
    if (!wq_p) {
        cudaGetSymbolAddress((void**)&wq_p, g_wq);
        cudaGetSymbolAddress((void**)&wk_p, g_wk);
        cudaGetSymbolAddress((void**)&wv_p, g_wv);
        cudaGetSymbolAddress((void**)&wp_p, g_wp);
    }

    dim3 gproj(Dn / 128, Mn / 128);       // (4, 64)
    proj_gemm<<<gproj, 256>>>(query, wq_p, bq, u_bias, v_bias, 0);
    proj_gemm<<<gproj, 256>>>(key,   wk_p, bk, nullptr, nullptr, 1);
    proj_gemm<<<gproj, 256>>>(value, wv_p, bv, nullptr, nullptr, 2);
    proj_gemm<<<gproj, 256>>>(pemb,  wp_p, nullptr, nullptr, nullptr, 3);

    dim3 gsc(Sn / 128, Sn / 128, BHn);    // (8, 8, 64)
    score_pos<<<gsc, 256>>>();            // pre-scaled pos, scattered -> g_sc

    dim3 gf(Sn / 128, BHn);               // (8, 64)
    attn_fused<<<gf, 256, FUSED_SMEM_BYTES>>>();

    out_gemm<<<gproj, 256>>>(bo, out);
}

// round 11
// speedup vs baseline: 2.3700x; 1.0861x over previous
#include <cuda_runtime.h>
#include <cuda_bf16.h>

// Problem constants
#define Bn   8
#define Sn   1024
#define Dn   512
#define Hn   8
#define DHn  64
#define BHn  (Bn * Hn)      // 64
#define Mn   (Bn * Sn)      // 8192
#define SCALE 0.044194173824159216f   // 1/sqrt(512)

#define KC    16     // real-k per smem stage (GEMM kernels)
#define AS    20     // A smem stride (u32): conflict-free frags
#define NS128 136    // B smem stride, BN=128: mod 32 == 8 -> conflict-free
#define QS    68     // fused: Q smem stride (mod 32 == 4)
#define KS    72     // fused: K/V smem stride (mod 32 == 8)
#define PS2   68     // fused: P smem stride (mod 32 == 4)

// Scratch (device globals — no allocation allowed). ~357 MB total.
// All activation tensors stored PRE-PACKED as (bf16 hi | bf16 lo<<16) u32.
static __device__ unsigned g_qu[Mn * Dn];   // pack(SCALE*(q + bq + u_bias))
static __device__ unsigned g_qv[Mn * Dn];   // pack(SCALE*(q + bq + v_bias))
static __device__ unsigned g_k[Mn * Dn];
static __device__ unsigned g_v[Mn * Dn];
static __device__ unsigned g_p[Mn * Dn];
static __device__ unsigned g_ctx[Mn * Dn];
static __device__ float    g_sc[(size_t)BHn * Sn * Sn];  // pre-scaled shifted pos
// Packed weights
static __device__ unsigned g_wq[Dn * Dn];
static __device__ unsigned g_wk[Dn * Dn];
static __device__ unsigned g_wv[Dn * Dn];
static __device__ unsigned g_wp[Dn * Dn];
static __device__ unsigned g_wo[Dn * Dn];

// ---------------------------------------------------------------------------
__device__ __forceinline__ unsigned pack_split(float x) {
    __nv_bfloat16 h = __float2bfloat16(x);
    float hf = __bfloat162float(h);
    __nv_bfloat16 l = __float2bfloat16(x - hf);
    return (unsigned)__bfloat16_as_ushort(h) |
           ((unsigned)__bfloat16_as_ushort(l) << 16);
}

__device__ __forceinline__ unsigned swap16(unsigned u) { return (u >> 16) | (u << 16); }

__device__ __forceinline__ void mma_bf16(float c[4], const unsigned a[4],
                                         unsigned b0, unsigned b1) {
    asm volatile(
        "mma.sync.aligned.m16n8k16.row.col.f32.bf16.bf16.f32 "
        "{%0,%1,%2,%3},{%4,%5,%6,%7},{%8,%9},{%0,%1,%2,%3};"
        : "+f"(c[0]), "+f"(c[1]), "+f"(c[2]), "+f"(c[3])
        : "r"(a[0]), "r"(a[1]), "r"(a[2]), "r"(a[3]), "r"(b0), "r"(b1));
}

__device__ __forceinline__ void load8f(float v[8], const float* __restrict__ p) {
    float4 a = *reinterpret_cast<const float4*>(p);
    float4 b = *reinterpret_cast<const float4*>(p + 4);
    v[0] = a.x; v[1] = a.y; v[2] = a.z; v[3] = a.w;
    v[4] = b.x; v[5] = b.y; v[6] = b.z; v[7] = b.w;
}

__device__ __forceinline__ void load8u(unsigned v[8], const unsigned* __restrict__ p) {
    uint4 a = *reinterpret_cast<const uint4*>(p);
    uint4 b = *reinterpret_cast<const uint4*>(p + 4);
    v[0] = a.x; v[1] = a.y; v[2] = a.z; v[3] = a.w;
    v[4] = b.x; v[5] = b.y; v[6] = b.z; v[7] = b.w;
}

// ---------------------------------------------------------------------------
// Pack ALL weights in one launch. grid = (Dn*Dn/256, 5).
// ---------------------------------------------------------------------------
__global__ void pack_all(const float* __restrict__ Wq, const float* __restrict__ Wk,
                         const float* __restrict__ Wv, const float* __restrict__ Wp,
                         const float* __restrict__ Wo) {
    const int sel = blockIdx.y;
    const float* src = (sel == 0) ? Wq : (sel == 1) ? Wk : (sel == 2) ? Wv
                     : (sel == 3) ? Wp : Wo;
    unsigned* dst = (sel == 0) ? g_wq : (sel == 1) ? g_wk : (sel == 2) ? g_wv
                  : (sel == 3) ? g_wp : g_wo;
    const int i = blockIdx.x * 256 + threadIdx.x;
    dst[i] = pack_split(src[i]);
}

// ---------------------------------------------------------------------------
// Warp compute on one KC=16 stage. Warp tile 64 x (NT*8).
// ---------------------------------------------------------------------------
template <int NT, int NS>
__device__ __forceinline__ void warp_mma_stage(const unsigned* __restrict__ A,
                                               const unsigned* __restrict__ B,
                                               int wm, int wn, int lane,
                                               float acc[4][NT][4]) {
    const int g = lane >> 2, kq = lane & 3;
    #pragma unroll
    for (int h = 0; h < 2; h++) {
        unsigned af[4][4];
        #pragma unroll
        for (int t = 0; t < 4; t++) {
            const unsigned* p = A + (wm + t * 16 + g) * AS + h * 8 + kq;
            af[t][0] = p[0]; af[t][1] = p[8 * AS];
            af[t][2] = p[4]; af[t][3] = p[8 * AS + 4];
        }
        #pragma unroll
        for (int u = 0; u < NT; u++) {
            const unsigned* q = B + (h * 8 + kq) * NS + wn + u * 8 + g;
            unsigned b0 = q[0], b1 = q[4 * NS];
            unsigned s0 = swap16(b0), s1 = swap16(b1);
            #pragma unroll
            for (int t = 0; t < 4; t++) {
                mma_bf16(acc[t][u], af[t], b0, b1);   // hi*hi + lo*lo
                mma_bf16(acc[t][u], af[t], s0, s1);   // hi*lo + lo*hi
            }
        }
    }
}

// ---------------------------------------------------------------------------
// Batched projection GEMM: grid (4, 64, 4); blockIdx.z selects the projection.
//   z=0: Q -> g_qu (SCALE*(.+bq+u)) and g_qv (SCALE*(.+bq+v))
//   z=1: K -> g_k; z=2: V -> g_v; z=3: P -> g_p (no bias)
// ---------------------------------------------------------------------------
__global__ __launch_bounds__(256, 2) void proj_gemm(
    const float* __restrict__ Xq, const float* __restrict__ Xk,
    const float* __restrict__ Xv, const float* __restrict__ Xp,
    const float* __restrict__ bq, const float* __restrict__ bk,
    const float* __restrict__ bv,
    const float* __restrict__ ub, const float* __restrict__ vb) {
    const int sel = blockIdx.z;
    const float* X = (sel == 0) ? Xq : (sel == 1) ? Xk : (sel == 2) ? Xv : Xp;
    const unsigned* Wpk = (sel == 0) ? g_wq : (sel == 1) ? g_wk : (sel == 2) ? g_wv : g_wp;
    const float* bias = (sel == 0) ? bq : (sel == 1) ? bk : (sel == 2) ? bv : nullptr;

    __shared__ unsigned Asm[2][128 * AS];
    __shared__ unsigned Bsm[2][KC * NS128];
    const int tid = threadIdx.x, lane = tid & 31, w = tid >> 5;
    const int wm = (w >> 2) * 64, wn = (w & 3) * 32;
    const int mb = blockIdx.y * 128, nb = blockIdx.x * 128;
    const int ar = tid >> 1, akc = (tid & 1) * 8;
    const int br = tid >> 4, bc = (tid & 15) * 8;
    const float* Ag = X + (size_t)(mb + ar) * Dn + akc;
    const unsigned* Bg = Wpk + (size_t)br * Dn + nb + bc;
    float av[8]; unsigned bv8[8];
    load8f(av, Ag); load8u(bv8, Bg);
    float acc[4][4][4] = {};
    int buf = 0;
    for (int k0 = 0; k0 < Dn; k0 += KC) {
        #pragma unroll
        for (int q = 0; q < 8; q++) {
            Asm[buf][ar * AS + akc + q] = pack_split(av[q]);
            Bsm[buf][br * NS128 + bc + q] = bv8[q];
        }
        __syncthreads();
        if (k0 + KC < Dn) {
            load8f(av, Ag + k0 + KC);
            load8u(bv8, Bg + (size_t)(k0 + KC) * Dn);
        }
        warp_mma_stage<4, NS128>(Asm[buf], Bsm[buf], wm, wn, lane, acc);
        buf ^= 1;
    }
    const int g = lane >> 2, kq = lane & 3;
    #pragma unroll
    for (int t = 0; t < 4; t++) {
        #pragma unroll
        for (int u = 0; u < 4; u++) {
            #pragma unroll
            for (int e = 0; e < 4; e++) {
                const int row = mb + wm + t * 16 + g + (e >= 2 ? 8 : 0);
                const int col = nb + wn + u * 8 + 2 * kq + (e & 1);
                const size_t idx = (size_t)row * Dn + col;
                float r = acc[t][u][e];
                if (bias) r += bias[col];
                if (sel == 0) {
                    g_qu[idx] = pack_split(SCALE * (r + ub[col]));
                    g_qv[idx] = pack_split(SCALE * (r + vb[col]));
                } else if (sel == 1) g_k[idx] = pack_split(r);
                else if (sel == 2)   g_v[idx] = pack_split(r);
                else                 g_p[idx] = pack_split(r);
            }
        }
    }
}

// ---------------------------------------------------------------------------
// Output GEMM: out = unpack(g_ctx) @ Wo + bo. Both operands pre-packed.
// ---------------------------------------------------------------------------
__global__ __launch_bounds__(256, 2) void out_gemm(const float* __restrict__ bias,
                                                   float* __restrict__ C) {
    __shared__ unsigned Asm[2][128 * AS];
    __shared__ unsigned Bsm[2][KC * NS128];
    const int tid = threadIdx.x, lane = tid & 31, w = tid >> 5;
    const int wm = (w >> 2) * 64, wn = (w & 3) * 32;
    const int mb = blockIdx.y * 128, nb = blockIdx.x * 128;
    const int ar = tid >> 1, akc = (tid & 1) * 8;
    const int br = tid >> 4, bc = (tid & 15) * 8;
    const unsigned* Ag = g_ctx + (size_t)(mb + ar) * Dn + akc;
    const unsigned* Bg = g_wo + (size_t)br * Dn + nb + bc;
    unsigned av[8], bv[8];
    load8u(av, Ag); load8u(bv, Bg);
    float acc[4][4][4] = {};
    int buf = 0;
    for (int k0 = 0; k0 < Dn; k0 += KC) {
        #pragma unroll
        for (int q = 0; q < 8; q++) {
            Asm[buf][ar * AS + akc + q] = av[q];
            Bsm[buf][br * NS128 + bc + q] = bv[q];
        }
        __syncthreads();
        if (k0 + KC < Dn) {
            load8u(av, Ag + k0 + KC);
            load8u(bv, Bg + (size_t)(k0 + KC) * Dn);
        }
        warp_mma_stage<4, NS128>(Asm[buf], Bsm[buf], wm, wn, lane, acc);
        buf ^= 1;
    }
    const int g = lane >> 2, kq = lane & 3;
    #pragma unroll
    for (int t = 0; t < 4; t++) {
        #pragma unroll
        for (int u = 0; u < 4; u++) {
            const int row = mb + wm + t * 16 + g;
            const int col = nb + wn + u * 8 + 2 * kq;
            const float b0 = bias[col], b1 = bias[col + 1];
            float2 lo; lo.x = acc[t][u][0] + b0; lo.y = acc[t][u][1] + b1;
            float2 hi; hi.x = acc[t][u][2] + b0; hi.y = acc[t][u][3] + b1;
            *reinterpret_cast<float2*>(C + (size_t)row * Dn + col) = lo;
            *reinterpret_cast<float2*>(C + (size_t)(row + 8) * Dn + col) = hi;
        }
    }
}

// ---------------------------------------------------------------------------
// Score pass 0, per (b,h): P[i,c]=SCALE*(q_i+vb).p_c scattered SHIFTED:
//   c >= S-1-i -> R[i, c-S+1+i];  c < S-1-i -> R[i-1, c+i+1] (dropped at i==0)
// R[i,i+1] never written (identically 0; masked at read time in attn_fused).
// ---------------------------------------------------------------------------
__global__ __launch_bounds__(256, 2) void score_pos() {
    const int bh = blockIdx.z;
    const int b = bh >> 3, h = bh & 7;
    const int ib = blockIdx.y * 128, jb = blockIdx.x * 128;
    const unsigned* Ag = g_qv + (size_t)(b * Sn + ib) * Dn + h * DHn;
    const unsigned* Bg = g_p + (size_t)(b * Sn + jb) * Dn + h * DHn;
    __shared__ unsigned Asm[2][128 * AS];
    __shared__ unsigned Bsm[2][KC * NS128];
    const int tid = threadIdx.x, lane = tid & 31, w = tid >> 5;
    const int wm = (w >> 2) * 64, wn = (w & 3) * 32;
    const int ar = tid >> 1, akc = (tid & 1) * 8;
    const unsigned* Agr = Ag + (size_t)ar * Dn + akc;
    const unsigned* Bgr = Bg + (size_t)ar * Dn + akc;   // transposed source
    unsigned av[8], bv[8];
    load8u(av, Agr); load8u(bv, Bgr);
    float acc[4][4][4] = {};
    int buf = 0;
    #pragma unroll
    for (int k0 = 0; k0 < DHn; k0 += KC) {
        #pragma unroll
        for (int q = 0; q < 8; q++) {
            Asm[buf][ar * AS + akc + q] = av[q];
            Bsm[buf][(akc + q) * NS128 + ar] = bv[q];
        }
        __syncthreads();
        if (k0 + KC < DHn) {
            load8u(av, Agr + k0 + KC);
            load8u(bv, Bgr + k0 + KC);
        }
        warp_mma_stage<4, NS128>(Asm[buf], Bsm[buf], wm, wn, lane, acc);
        buf ^= 1;
    }
    const size_t base = (size_t)bh * Sn * Sn;
    const int g = lane >> 2, kq = lane & 3;
    #pragma unroll
    for (int t = 0; t < 4; t++) {
        #pragma unroll
        for (int u = 0; u < 4; u++) {
            #pragma unroll
            for (int e = 0; e < 4; e++) {
                const int i = ib + wm + t * 16 + g + (e >= 2 ? 8 : 0);
                const int j = jb + wn + u * 8 + 2 * kq + (e & 1);
                const float val = acc[t][u][e];
                if (j >= Sn - 1 - i)
                    g_sc[base + (size_t)i * Sn + (j - Sn + 1 + i)] = val;
                else if (i > 0)
                    g_sc[base + (size_t)(i - 1) * Sn + (j + i + 1)] = val;
            }
        }
    }
}

// ---------------------------------------------------------------------------
// Fused flash attention, j-tile = 64 for 2 CTAs/SM.
// Per (b,h, 128-row q strip). 256 threads, 8 warps (2 m-groups x 4 n-warps).
// K stored transposed [k][j]; V stored transposed [d][j] (conflict-free
// stores; V frag reads 2-way). Psm/Qsm stride 68 (conflict-free A frags).
// ---------------------------------------------------------------------------
#define Q_U32   (128 * QS)       // 8704
#define KV_U32  (64 * KS)        // 4608
#define P_U32   (128 * PS2)      // 8704
#define RED_U32 512
#define FUSED_SMEM_BYTES ((Q_U32 + KV_U32 + P_U32 + RED_U32) * 4)   // ~90 KB

__global__ __launch_bounds__(256, 2) void attn_fused() {
    extern __shared__ unsigned sm[];
    unsigned* Qsm  = sm;
    unsigned* KVsm = sm + Q_U32;
    unsigned* Psm  = sm + Q_U32 + KV_U32;
    float*    redf = (float*)(sm + Q_U32 + KV_U32 + P_U32);   // [4][128]

    const int bh = blockIdx.y;
    const int b = bh >> 3, h = bh & 7;
    const int ib = blockIdx.x * 128;
    const int tid = threadIdx.x, lane = tid & 31, w = tid >> 5;
    const int g = lane >> 2, kq = lane & 3;
    const int wm = (w >> 2) * 64;
    const int wnS = (w & 3) * 16, wnV = (w & 3) * 16;
    const size_t scbase = (size_t)bh * Sn * Sn;

    // Load Q strip (pre-packed, pre-scaled, u_bias folded).
    {
        const int r = tid >> 1, off = (tid & 1) * 32;
        const unsigned* src = g_qu + (size_t)(b * Sn + ib + r) * Dn + h * DHn + off;
        #pragma unroll
        for (int c = 0; c < 32; c += 8) {
            unsigned v[8]; load8u(v, src + c);
            #pragma unroll
            for (int q = 0; q < 8; q++) Qsm[r * QS + off + c + q] = v[q];
        }
    }

    float m_reg[8], lp[8];
    #pragma unroll
    for (int i = 0; i < 8; i++) { m_reg[i] = -1e30f; lp[i] = 0.f; }
    float acc_o[4][2][4] = {};

    const int jld = tid & 63, kld = (tid >> 6) * 16;   // tile loader mapping

    for (int jt = 0; jt < 16; jt++) {
        const int j0 = jt * 64;
        __syncthreads();   // prev AV mma done before KVsm overwrite
        // K tile (64 j x 64 k) -> transposed KVsm[k][j], stride KS. Conflict-free.
        {
            const unsigned* src = g_k + (size_t)(b * Sn + j0 + jld) * Dn + h * DHn + kld;
            unsigned v[16]; load8u(v, src); load8u(v + 8, src + 8);
            #pragma unroll
            for (int c = 0; c < 16; c++) KVsm[(kld + c) * KS + jld] = v[c];
        }
        __syncthreads();
        // Content score mma: 64 real k, NT=2 (16 cols/warp).
        float acc_s[4][2][4] = {};
        #pragma unroll
        for (int hh = 0; hh < 8; hh++) {
            unsigned af[4][4];
            #pragma unroll
            for (int t = 0; t < 4; t++) {
                const unsigned* p = Qsm + (wm + t * 16 + g) * QS + hh * 8 + kq;
                af[t][0] = p[0]; af[t][1] = p[8 * QS];
                af[t][2] = p[4]; af[t][3] = p[8 * QS + 4];
            }
            #pragma unroll
            for (int u = 0; u < 2; u++) {
                const unsigned* q = KVsm + (hh * 8 + kq) * KS + wnS + u * 8 + g;
                unsigned b0 = q[0], b1 = q[4 * KS];
                unsigned s0 = swap16(b0), s1 = swap16(b1);
                #pragma unroll
                for (int t = 0; t < 4; t++) {
                    mma_bf16(acc_s[t][u], af[t], b0, b1);
                    mma_bf16(acc_s[t][u], af[t], s0, s1);
                }
            }
        }
        // Add pre-scaled pos bias (j==i+1 slot forced 0), row max.
        float pm[8];
        #pragma unroll
        for (int i = 0; i < 8; i++) pm[i] = -1e30f;
        #pragma unroll
        for (int t = 0; t < 4; t++) {
            #pragma unroll
            for (int rh = 0; rh < 2; rh++) {
                const int i = ib + wm + t * 16 + g + rh * 8;
                const float* row = g_sc + scbase + (size_t)i * Sn + j0;
                const int idx = t * 2 + rh;
                #pragma unroll
                for (int u = 0; u < 2; u++) {
                    const int jl = wnS + u * 8 + 2 * kq;
                    float2 pv = *reinterpret_cast<const float2*>(row + jl);
                    const int jg = j0 + jl;
                    float p0 = (jg == i + 1) ? 0.f : pv.x;
                    float p1 = (jg + 1 == i + 1) ? 0.f : pv.y;
                    float s0v = acc_s[t][u][rh * 2 + 0] + p0;
                    float s1v = acc_s[t][u][rh * 2 + 1] + p1;
                    acc_s[t][u][rh * 2 + 0] = s0v;
                    acc_s[t][u][rh * 2 + 1] = s1v;
                    pm[idx] = fmaxf(pm[idx], fmaxf(s0v, s1v));
                }
            }
        }
        #pragma unroll
        for (int i = 0; i < 8; i++) {
            pm[i] = fmaxf(pm[i], __shfl_xor_sync(0xffffffffu, pm[i], 1));
            pm[i] = fmaxf(pm[i], __shfl_xor_sync(0xffffffffu, pm[i], 2));
        }
        if (kq == 0) {
            #pragma unroll
            for (int t = 0; t < 4; t++)
                #pragma unroll
                for (int rh = 0; rh < 2; rh++)
                    redf[(w & 3) * 128 + wm + t * 16 + g + rh * 8] = pm[t * 2 + rh];
        }
        __syncthreads();
        float alpha[8];
        #pragma unroll
        for (int t = 0; t < 4; t++) {
            #pragma unroll
            for (int rh = 0; rh < 2; rh++) {
                const int r = wm + t * 16 + g + rh * 8, idx = t * 2 + rh;
                float tm = fmaxf(fmaxf(redf[r], redf[128 + r]),
                                 fmaxf(redf[256 + r], redf[384 + r]));
                float mn = fmaxf(m_reg[idx], tm);
                alpha[idx] = __expf(m_reg[idx] - mn);
                m_reg[idx] = mn;
                lp[idx] *= alpha[idx];
            }
        }
        #pragma unroll
        for (int t = 0; t < 4; t++)
            #pragma unroll
            for (int u = 0; u < 2; u++) {
                acc_o[t][u][0] *= alpha[t * 2];     acc_o[t][u][1] *= alpha[t * 2];
                acc_o[t][u][2] *= alpha[t * 2 + 1]; acc_o[t][u][3] *= alpha[t * 2 + 1];
            }
        // P = exp(s - m); partial row sums; pack into Psm.
        #pragma unroll
        for (int t = 0; t < 4; t++) {
            #pragma unroll
            for (int rh = 0; rh < 2; rh++) {
                const int idx = t * 2 + rh;
                const int rloc = wm + t * 16 + g + rh * 8;
                #pragma unroll
                for (int u = 0; u < 2; u++) {
                    const int jl = wnS + u * 8 + 2 * kq;
                    float p0 = __expf(acc_s[t][u][rh * 2 + 0] - m_reg[idx]);
                    float p1 = __expf(acc_s[t][u][rh * 2 + 1] - m_reg[idx]);
                    lp[idx] += p0 + p1;
                    Psm[rloc * PS2 + jl] = pack_split(p0);
                    Psm[rloc * PS2 + jl + 1] = pack_split(p1);
                }
            }
        }
        __syncthreads();   // Psm ready; K reads done -> reuse KVsm for V
        // V tile (64 j x 64 d) -> transposed KVsm[d][j], stride KS.
        {
            const unsigned* src = g_v + (size_t)(b * Sn + j0 + jld) * Dn + h * DHn + kld;
            unsigned v[16]; load8u(v, src); load8u(v + 8, src + 8);
            #pragma unroll
            for (int c = 0; c < 16; c++) KVsm[(kld + c) * KS + jld] = v[c];
        }
        __syncthreads();
        // AV mma: 64 real k (this j-tile), NT=2, V read as [n=d][k=j].
        #pragma unroll
        for (int hh = 0; hh < 8; hh++) {
            unsigned af[4][4];
            #pragma unroll
            for (int t = 0; t < 4; t++) {
                const unsigned* p = Psm + (wm + t * 16 + g) * PS2 + hh * 8 + kq;
                af[t][0] = p[0]; af[t][1] = p[8 * PS2];
                af[t][2] = p[4]; af[t][3] = p[8 * PS2 + 4];
            }
            #pragma unroll
            for (int u = 0; u < 2; u++) {
                const unsigned* q = KVsm + (wnV + u * 8 + g) * KS + hh * 8 + kq;
                unsigned b0 = q[0], b1 = q[4];
                unsigned s0 = swap16(b0), s1 = swap16(b1);
                #pragma unroll
                for (int t = 0; t < 4; t++) {
                    mma_bf16(acc_o[t][u], af[t], b0, b1);
                    mma_bf16(acc_o[t][u], af[t], s0, s1);
                }
            }
        }
    }
    // Final row-sum reduction and normalized packed output.
    #pragma unroll
    for (int i = 0; i < 8; i++) {
        lp[i] += __shfl_xor_sync(0xffffffffu, lp[i], 1);
        lp[i] += __shfl_xor_sync(0xffffffffu, lp[i], 2);
    }
    __syncthreads();
    if (kq == 0) {
        #pragma unroll
        for (int t = 0; t < 4; t++)
            #pragma unroll
            for (int rh = 0; rh < 2; rh++)
                redf[(w & 3) * 128 + wm + t * 16 + g + rh * 8] = lp[t * 2 + rh];
    }
    __syncthreads();
    float inv[8];
    #pragma unroll
    for (int t = 0; t < 4; t++) {
        #pragma unroll
        for (int rh = 0; rh < 2; rh++) {
            const int r = wm + t * 16 + g + rh * 8;
            inv[t * 2 + rh] = 1.0f / (redf[r] + redf[128 + r] + redf[256 + r] + redf[384 + r]);
        }
    }
    #pragma unroll
    for (int t = 0; t < 4; t++) {
        #pragma unroll
        for (int u = 0; u < 2; u++) {
            #pragma unroll
            for (int e = 0; e < 4; e++) {
                const int i = ib + wm + t * 16 + g + (e >= 2 ? 8 : 0);
                const int col = h * DHn + wnV + u * 8 + 2 * kq + (e & 1);
                g_ctx[(size_t)(b * Sn + i) * Dn + col] =
                    pack_split(acc_o[t][u][e] * inv[t * 2 + (e >= 2 ? 1 : 0)]);
            }
        }
    }
}

// ---------------------------------------------------------------------------
extern "C" void kernel_launch(void* const* d_in, const int* in_sizes, int n_in,
                              void* d_out, int out_size) {
    (void)in_sizes; (void)n_in; (void)out_size;
    const float* query = (const float*)d_in[0];
    const float* key   = (const float*)d_in[1];
    const float* value = (const float*)d_in[2];
    const float* pemb  = (const float*)d_in[3];
    const float* Wq    = (const float*)d_in[4];
    const float* bq    = (const float*)d_in[5];
    const float* Wk    = (const float*)d_in[6];
    const float* bk    = (const float*)d_in[7];
    const float* Wv    = (const float*)d_in[8];
    const float* bv    = (const float*)d_in[9];
    const float* Wp    = (const float*)d_in[10];
    const float* u_bias = (const float*)d_in[11];
    const float* v_bias = (const float*)d_in[12];
    const float* Wo    = (const float*)d_in[13];
    const float* bo    = (const float*)d_in[14];
    float* out = (float*)d_out;

    cudaFuncSetAttribute(attn_fused, cudaFuncAttributeMaxDynamicSharedMemorySize,
                         FUSED_SMEM_BYTES);

    dim3 gpack(Dn * Dn / 256, 5);
    pack_all<<<gpack, 256>>>(Wq, Wk, Wv, Wp, Wo);

    dim3 gproj(Dn / 128, Mn / 128, 4);    // (4, 64, 4) — all projections, one launch
    proj_gemm<<<gproj, 256>>>(query, key, value, pemb, bq, bk, bv, u_bias, v_bias);

    dim3 gsc(Sn / 128, Sn / 128, BHn);    // (8, 8, 64)
    score_pos<<<gsc, 256>>>();            // pre-scaled pos, scattered -> g_sc

    dim3 gf(Sn / 128, BHn);               // (8, 64)
    attn_fused<<<gf, 256, FUSED_SMEM_BYTES>>>();

    out_gemm<<<dim3(Dn / 128, Mn / 128), 256>>>(bo, out);
}